// round 1
// baseline (speedup 1.0000x reference)
#include <cuda_runtime.h>
#include <cuda_bf16.h>
#include <math.h>

// ---------------------------------------------------------------------------
// MambaMIL_2D forward, fp32 SIMT baseline.
// Shapes (B=1): L=2048, IN=1024, D_MODEL=512, D_INNER=1024, D_STATE=16,
// DT_RANK=32, D_CONV=4, N_LAYERS=2. Output [11,128,128] fp32.
// ---------------------------------------------------------------------------

#define L 2048
#define DM 512
#define DI 1024
#define DS 16
#define DTR 32

// ------------------------------- scratch ----------------------------------
__device__ float g_h   [L * DM];
__device__ float g_hn  [L * DM];
__device__ float g_xz  [L * 2 * DI];
__device__ float g_xi  [L * DI];
__device__ float g_dbc [L * 64];
__device__ float g_delta[L * DI];
__device__ float g_y   [L * DI];
__device__ float g_t1  [L * 128];
__device__ float g_s   [L];
__device__ float g_attw[L];
__device__ float g_pooled[DM];
__device__ float g_part[2 * 1024 * 1024];   // split-K partials (8MB)
__device__ float g_c1[256 * 16];
__device__ float g_c2[128 * 256];
__device__ float g_c3[64 * 1024];
__device__ float g_c4[32 * 4096];

// ------------------------------ math helpers ------------------------------
__device__ __forceinline__ float geluf(float x) {
    return 0.5f * x * (1.f + erff(x * 0.70710678118654752f));
}
__device__ __forceinline__ float softplusf(float x) {
    return (x > 20.f) ? x : log1pf(__expf(x));
}
__device__ __forceinline__ float siluf(float x) {
    return x / (1.f + __expf(-x));
}

// epilogues: 0 none, 1 gelu+bias+posemb, 2 residual add (reads C), 3 bias+softplus, 4 bias+tanh
__device__ __forceinline__ float apply_epi(float v, int row, int col, int ldc,
                                           const float* C, int epi,
                                           const float* bias, const float* aux0,
                                           const float* aux1, const float* aux2) {
    switch (epi) {
        case 1:
            v += bias[col];
            v = geluf(v);
            v += aux0[row * 2 + 0] * aux1[col] + aux0[row * 2 + 1] * aux1[512 + col] + aux2[col];
            return v;
        case 2: return v + C[(size_t)row * ldc + col];
        case 3: return softplusf(v + bias[col]);
        case 4: return tanhf(v + bias[col]);
        default: return v;
    }
}

// ------------------------------ SGEMM 128x128 ------------------------------
// C[M,N] = A[M,K](lda) * B[K,N](ldb), fp32, BM=BN=128, BK=8, 256 thr, 8x8/thr.
// Assumes M%128==0, K%8==0, N%4==0. Guards N (zero-fill + store guard).
__global__ __launch_bounds__(256) void sgemm128_k(
    int M, int N, int K,
    const float* __restrict__ A, int lda,
    const float* __restrict__ B, int ldb,
    float* __restrict__ C, int ldc,
    int epi, const float* __restrict__ bias,
    const float* __restrict__ aux0, const float* __restrict__ aux1,
    const float* __restrict__ aux2)
{
    __shared__ float As[8][128];
    __shared__ float Bs[8][128];
    int tid = threadIdx.x;
    int bm = blockIdx.y, bn = blockIdx.x;

    int aRow = tid >> 1;           // 0..127
    int aCol = (tid & 1) * 4;      // 0 or 4
    int bRow = tid >> 5;           // 0..7
    int bCol = (tid & 31) * 4;     // 0..124
    int tr = tid >> 4;             // 0..15
    int tc = tid & 15;             // 0..15

    const float* Ap = A + (size_t)(bm * 128 + aRow) * lda + aCol;
    int gcolB = bn * 128 + bCol;

    float acc[8][8];
#pragma unroll
    for (int i = 0; i < 8; i++)
#pragma unroll
        for (int j = 0; j < 8; j++) acc[i][j] = 0.f;

    for (int k0 = 0; k0 < K; k0 += 8) {
        float4 a4 = *(const float4*)(Ap + k0);
        As[aCol + 0][aRow] = a4.x;
        As[aCol + 1][aRow] = a4.y;
        As[aCol + 2][aRow] = a4.z;
        As[aCol + 3][aRow] = a4.w;
        float4 b4 = make_float4(0.f, 0.f, 0.f, 0.f);
        if (gcolB < N) b4 = *(const float4*)(B + (size_t)(k0 + bRow) * ldb + gcolB);
        *(float4*)&Bs[bRow][bCol] = b4;
        __syncthreads();
#pragma unroll
        for (int kk = 0; kk < 8; kk++) {
            float ra[8], rb[8];
            *(float4*)&ra[0] = *(const float4*)&As[kk][tr * 8];
            *(float4*)&ra[4] = *(const float4*)&As[kk][tr * 8 + 4];
            *(float4*)&rb[0] = *(const float4*)&Bs[kk][tc * 8];
            *(float4*)&rb[4] = *(const float4*)&Bs[kk][tc * 8 + 4];
#pragma unroll
            for (int i = 0; i < 8; i++)
#pragma unroll
                for (int j = 0; j < 8; j++)
                    acc[i][j] = fmaf(ra[i], rb[j], acc[i][j]);
        }
        __syncthreads();
    }

#pragma unroll
    for (int i = 0; i < 8; i++) {
        int row = bm * 128 + tr * 8 + i;
#pragma unroll
        for (int j = 0; j < 8; j++) {
            int col = bn * 128 + tc * 8 + j;
            if (col < N) {
                float v = apply_epi(acc[i][j], row, col, ldc, C, epi, bias, aux0, aux1, aux2);
                C[(size_t)row * ldc + col] = v;
            }
        }
    }
}

// ------------------------------ SGEMM 64x64 --------------------------------
// BM=BN=64, BK=16, 256 thr, 4x4/thr. Optional split-K: gridDim.z = slices,
// each slice writes raw partial to C + z*M*N (ldc must be N for that path).
__global__ __launch_bounds__(256) void sgemm64_k(
    int M, int N, int K,
    const float* __restrict__ A, int lda,
    const float* __restrict__ B, int ldb,
    float* __restrict__ C, int ldc,
    int epi, const float* __restrict__ bias,
    const float* __restrict__ aux0, const float* __restrict__ aux1,
    const float* __restrict__ aux2)
{
    __shared__ float As[16][64];
    __shared__ float Bs[16][64];
    int tid = threadIdx.x;
    int bm = blockIdx.y, bn = blockIdx.x, bz = blockIdx.z;
    int slices = gridDim.z;
    int Ks = K / slices;
    int kbase = bz * Ks;

    int aRow = tid >> 2;          // 0..63
    int aCol = (tid & 3) * 4;     // 0..12
    int bRow = tid >> 4;          // 0..15
    int bCol = (tid & 15) * 4;    // 0..60
    int tr = tid >> 4;            // 0..15
    int tc = tid & 15;            // 0..15

    const float* Ap = A + (size_t)(bm * 64 + aRow) * lda + kbase + aCol;
    int gcolB = bn * 64 + bCol;

    float acc[4][4];
#pragma unroll
    for (int i = 0; i < 4; i++)
#pragma unroll
        for (int j = 0; j < 4; j++) acc[i][j] = 0.f;

    for (int k0 = 0; k0 < Ks; k0 += 16) {
        float4 a4 = *(const float4*)(Ap + k0);
        As[aCol + 0][aRow] = a4.x;
        As[aCol + 1][aRow] = a4.y;
        As[aCol + 2][aRow] = a4.z;
        As[aCol + 3][aRow] = a4.w;
        float4 b4 = make_float4(0.f, 0.f, 0.f, 0.f);
        if (gcolB < N) b4 = *(const float4*)(B + (size_t)(kbase + k0 + bRow) * ldb + gcolB);
        *(float4*)&Bs[bRow][bCol] = b4;
        __syncthreads();
#pragma unroll
        for (int kk = 0; kk < 16; kk++) {
            float4 ra = *(const float4*)&As[kk][tr * 4];
            float4 rb = *(const float4*)&Bs[kk][tc * 4];
            float raa[4] = {ra.x, ra.y, ra.z, ra.w};
            float rbb[4] = {rb.x, rb.y, rb.z, rb.w};
#pragma unroll
            for (int i = 0; i < 4; i++)
#pragma unroll
                for (int j = 0; j < 4; j++)
                    acc[i][j] = fmaf(raa[i], rbb[j], acc[i][j]);
        }
        __syncthreads();
    }

    if (slices == 1) {
#pragma unroll
        for (int i = 0; i < 4; i++) {
            int row = bm * 64 + tr * 4 + i;
#pragma unroll
            for (int j = 0; j < 4; j++) {
                int col = bn * 64 + tc * 4 + j;
                if (col < N) {
                    float v = apply_epi(acc[i][j], row, col, ldc, C, epi, bias, aux0, aux1, aux2);
                    C[(size_t)row * ldc + col] = v;
                }
            }
        }
    } else {
        float* Cp = C + (size_t)bz * M * N;
#pragma unroll
        for (int i = 0; i < 4; i++) {
            int row = bm * 64 + tr * 4 + i;
#pragma unroll
            for (int j = 0; j < 4; j++) {
                int col = bn * 64 + tc * 4 + j;
                if (col < N) Cp[(size_t)row * N + col] = acc[i][j];
            }
        }
    }
}

// reduce split-K partials + epilogue
__global__ void reduce_k(const float* __restrict__ part, float* __restrict__ out,
                         int MN, int N, int slices, int epi, const float* __restrict__ bias)
{
    int idx = blockIdx.x * blockDim.x + threadIdx.x;
    if (idx >= MN) return;
    float v = 0.f;
    for (int s = 0; s < slices; s++) v += part[(size_t)s * MN + idx];
    int col = idx % N;
    if (epi == 4) v = tanhf(v + bias[col]);
    out[idx] = v;
}

// ------------------------------- RMSNorm -----------------------------------
__global__ __launch_bounds__(128) void rms_k(const float* __restrict__ h,
                                             const float* __restrict__ w,
                                             float* __restrict__ out)
{
    int t = blockIdx.x, tid = threadIdx.x;
    float v[4]; float ss = 0.f;
#pragma unroll
    for (int i = 0; i < 4; i++) {
        v[i] = h[(size_t)t * DM + tid + i * 128];
        ss += v[i] * v[i];
    }
#pragma unroll
    for (int off = 16; off > 0; off >>= 1) ss += __shfl_xor_sync(0xffffffffu, ss, off);
    __shared__ float sm[4];
    if ((tid & 31) == 0) sm[tid >> 5] = ss;
    __syncthreads();
    float tot = sm[0] + sm[1] + sm[2] + sm[3];
    float r = rsqrtf(tot / (float)DM + 1e-5f);
#pragma unroll
    for (int i = 0; i < 4; i++) {
        int c = tid + i * 128;
        out[(size_t)t * DM + c] = v[i] * r * w[c];
    }
}

// ------------------------------- LayerNorm ---------------------------------
__global__ __launch_bounds__(128) void ln_k(const float* __restrict__ h,
                                            const float* __restrict__ w,
                                            const float* __restrict__ b,
                                            float* __restrict__ out)
{
    int t = blockIdx.x, tid = threadIdx.x;
    float v[4]; float s1 = 0.f, s2 = 0.f;
#pragma unroll
    for (int i = 0; i < 4; i++) {
        v[i] = h[(size_t)t * DM + tid + i * 128];
        s1 += v[i]; s2 += v[i] * v[i];
    }
#pragma unroll
    for (int off = 16; off > 0; off >>= 1) {
        s1 += __shfl_xor_sync(0xffffffffu, s1, off);
        s2 += __shfl_xor_sync(0xffffffffu, s2, off);
    }
    __shared__ float a1[4], a2[4];
    if ((tid & 31) == 0) { a1[tid >> 5] = s1; a2[tid >> 5] = s2; }
    __syncthreads();
    s1 = a1[0] + a1[1] + a1[2] + a1[3];
    s2 = a2[0] + a2[1] + a2[2] + a2[3];
    float mean = s1 / (float)DM;
    float var = s2 / (float)DM - mean * mean;
    float r = rsqrtf(var + 1e-5f);
#pragma unroll
    for (int i = 0; i < 4; i++) {
        int c = tid + i * 128;
        out[(size_t)t * DM + c] = (v[i] - mean) * r * w[c] + b[c];
    }
}

// --------------------------- depthwise conv + silu -------------------------
__global__ __launch_bounds__(256) void conv_silu_k(const float* __restrict__ xz,
                                                   const float* __restrict__ cw,
                                                   const float* __restrict__ cb,
                                                   float* __restrict__ xi)
{
    int idx = blockIdx.x * 256 + threadIdx.x;   // L*DI threads
    int t = idx >> 10, d = idx & 1023;
    float w0 = cw[d * 4 + 0], w1 = cw[d * 4 + 1], w2 = cw[d * 4 + 2], w3 = cw[d * 4 + 3];
    float acc = cb[d];
    if (t >= 3) acc = fmaf(xz[(size_t)(t - 3) * 2048 + d], w0, acc);
    if (t >= 2) acc = fmaf(xz[(size_t)(t - 2) * 2048 + d], w1, acc);
    if (t >= 1) acc = fmaf(xz[(size_t)(t - 1) * 2048 + d], w2, acc);
    acc = fmaf(xz[(size_t)t * 2048 + d], w3, acc);
    xi[idx] = siluf(acc);
}

// ------------------------------ selective scan ------------------------------
// block = 128 threads = 8 d-channels x 16 states. Sequential over t in chunks
// of 64 staged through shared memory. y = (sum_n h*C + xi*D) * silu(z).
__global__ __launch_bounds__(128) void scan_k(
    const float* __restrict__ delta, const float* __restrict__ xi,
    const float* __restrict__ dbc, const float* __restrict__ xz,
    const float* __restrict__ alog, const float* __restrict__ Dp,
    float* __restrict__ y)
{
    __shared__ float sd[64][8], sx[64][8], sz[64][8], sy[64][8];
    __shared__ float sBC[64][32];
    int tid = threadIdx.x;
    int d0 = blockIdx.x * 8;
    int dloc = tid >> 4;
    int n = tid & 15;
    int d = d0 + dloc;
    float Adn = -__expf(alog[d * DS + n]);
    float Dv = Dp[d];
    float h = 0.f;

    for (int t0 = 0; t0 < L; t0 += 64) {
#pragma unroll
        for (int i = 0; i < 4; i++) {
            int e = tid + i * 128; int r = e >> 3, c = e & 7;
            sd[r][c] = delta[(size_t)(t0 + r) * DI + d0 + c];
            sx[r][c] = xi[(size_t)(t0 + r) * DI + d0 + c];
            sz[r][c] = xz[(size_t)(t0 + r) * 2048 + DI + d0 + c];
        }
#pragma unroll
        for (int i = 0; i < 16; i++) {
            int e = tid + i * 128; int r = e >> 5, c = e & 31;
            sBC[r][c] = dbc[(size_t)(t0 + r) * 64 + 32 + c];
        }
        __syncthreads();
#pragma unroll 4
        for (int tt = 0; tt < 64; tt++) {
            float dl = sd[tt][dloc];
            float xv = sx[tt][dloc];
            float a = __expf(dl * Adn);
            float bx = dl * xv * sBC[tt][n];
            h = fmaf(a, h, bx);
            float p = h * sBC[tt][16 + n];
            p += __shfl_xor_sync(0xffffffffu, p, 8);
            p += __shfl_xor_sync(0xffffffffu, p, 4);
            p += __shfl_xor_sync(0xffffffffu, p, 2);
            p += __shfl_xor_sync(0xffffffffu, p, 1);
            if (n == 0) {
                float zz = sz[tt][dloc];
                sy[tt][dloc] = (p + xv * Dv) * siluf(zz);
            }
        }
        __syncthreads();
#pragma unroll
        for (int i = 0; i < 4; i++) {
            int e = tid + i * 128; int r = e >> 3, c = e & 7;
            y[(size_t)(t0 + r) * DI + d0 + c] = sy[r][c];
        }
        __syncthreads();
    }
}

// -------------------------- attention score / softmax / pool ---------------
__global__ __launch_bounds__(256) void score_k(const float* __restrict__ t1,
                                               const float* __restrict__ Wa2,
                                               const float* __restrict__ ba2,
                                               float* __restrict__ s)
{
    int gw = (blockIdx.x * 256 + threadIdx.x) >> 5;
    int lane = threadIdx.x & 31;
    const float* row = t1 + (size_t)gw * 128;
    float acc = 0.f;
#pragma unroll
    for (int i = 0; i < 4; i++) acc = fmaf(row[lane + i * 32], Wa2[lane + i * 32], acc);
#pragma unroll
    for (int off = 16; off > 0; off >>= 1) acc += __shfl_xor_sync(0xffffffffu, acc, off);
    if (lane == 0) s[gw] = acc + ba2[0];
}

__global__ __launch_bounds__(1024) void softmax_k(const float* __restrict__ s,
                                                  float* __restrict__ w)
{
    int tid = threadIdx.x;
    __shared__ float red[32];
    __shared__ float bres;
    float a = s[tid], b = s[tid + 1024];
    float m = fmaxf(a, b);
#pragma unroll
    for (int off = 16; off > 0; off >>= 1) m = fmaxf(m, __shfl_xor_sync(0xffffffffu, m, off));
    if ((tid & 31) == 0) red[tid >> 5] = m;
    __syncthreads();
    if (tid < 32) {
        float x = red[tid];
#pragma unroll
        for (int off = 16; off > 0; off >>= 1) x = fmaxf(x, __shfl_xor_sync(0xffffffffu, x, off));
        if (tid == 0) bres = x;
    }
    __syncthreads();
    float M = bres;
    float ea = __expf(a - M), eb = __expf(b - M);
    float ss = ea + eb;
#pragma unroll
    for (int off = 16; off > 0; off >>= 1) ss += __shfl_xor_sync(0xffffffffu, ss, off);
    __syncthreads();
    if ((tid & 31) == 0) red[tid >> 5] = ss;
    __syncthreads();
    if (tid < 32) {
        float x = red[tid];
#pragma unroll
        for (int off = 16; off > 0; off >>= 1) x += __shfl_xor_sync(0xffffffffu, x, off);
        if (tid == 0) bres = x;
    }
    __syncthreads();
    float inv = 1.f / bres;
    w[tid] = ea * inv;
    w[tid + 1024] = eb * inv;
}

__global__ __launch_bounds__(256) void pool_k(const float* __restrict__ attw,
                                              const float* __restrict__ hn,
                                              float* __restrict__ pooled)
{
    int c = blockIdx.x * 256 + threadIdx.x;
    float acc = 0.f;
#pragma unroll 8
    for (int t = 0; t < L; t++) acc = fmaf(attw[t], hn[(size_t)t * DM + c], acc);
    pooled[c] = acc;
}

// ---------------------------- ConvTranspose2d ------------------------------
// weight layout [Cin, Cout, 4, 4]; out[co,oy,ox] += in[ci,iy,ix]*w[ci,co,ky,kx]
// with iy=(oy+P-ky)/S when divisible and in range.
__global__ void convt_k(const float* __restrict__ in, const float* __restrict__ w,
                        const float* __restrict__ b, float* __restrict__ out,
                        int Cin, int Cout, int Hin, int Hout, int S, int P,
                        int do_relu, int total)
{
    int idx = blockIdx.x * blockDim.x + threadIdx.x;
    if (idx >= total) return;
    int hw = Hout * Hout;
    int co = idx / hw;
    int r = idx % hw;
    int oy = r / Hout, ox = r % Hout;
    float acc = b[co];
    for (int ky = 0; ky < 4; ky++) {
        int ry = oy + P - ky;
        if (ry < 0 || (ry % S)) continue;
        int iy = ry / S;
        if (iy >= Hin) continue;
        for (int kx = 0; kx < 4; kx++) {
            int rx = ox + P - kx;
            if (rx < 0 || (rx % S)) continue;
            int ix = rx / S;
            if (ix >= Hin) continue;
            const float* wp = w + co * 16 + ky * 4 + kx;
            const float* ip = in + iy * Hin + ix;
            float ps = 0.f;
            for (int ci = 0; ci < Cin; ci++)
                ps = fmaf(ip[ci * Hin * Hin], wp[(size_t)ci * Cout * 16], ps);
            acc += ps;
        }
    }
    out[idx] = do_relu ? fmaxf(acc, 0.f) : acc;
}

// ------------------------------- launcher ----------------------------------
extern "C" void kernel_launch(void* const* d_in, const int* in_sizes, int n_in,
                              void* d_out, int out_size)
{
    const float* x       = (const float*)d_in[0];
    const float* coords  = (const float*)d_in[1];
    const float* W_fc1   = (const float*)d_in[2];
    const float* b_fc1   = (const float*)d_in[3];
    const float* W_pos   = (const float*)d_in[4];
    const float* b_pos   = (const float*)d_in[5];
    const float* in_w    = (const float*)d_in[6];   // [2,512,2048]
    const float* conv_w  = (const float*)d_in[7];   // [2,1024,1,4]
    const float* conv_b  = (const float*)d_in[8];   // [2,1024]
    const float* x_w     = (const float*)d_in[9];   // [2,1024,64]
    const float* dt_w    = (const float*)d_in[10];  // [2,32,1024]
    const float* dt_b    = (const float*)d_in[11];  // [2,1024]
    const float* A_log   = (const float*)d_in[12];  // [2,1024,16]
    const float* Dp      = (const float*)d_in[13];  // [2,1024]
    const float* out_w   = (const float*)d_in[14];  // [2,1024,512]
    const float* rms_w   = (const float*)d_in[15];  // [2,512]
    const float* ln_w    = (const float*)d_in[16];
    const float* ln_b    = (const float*)d_in[17];
    const float* Wa1     = (const float*)d_in[18];
    const float* ba1     = (const float*)d_in[19];
    const float* Wa2     = (const float*)d_in[20];
    const float* ba2     = (const float*)d_in[21];
    const float* ct1_w   = (const float*)d_in[22];
    const float* ct1_b   = (const float*)d_in[23];
    const float* ct2_w   = (const float*)d_in[24];
    const float* ct2_b   = (const float*)d_in[25];
    const float* ct3_w   = (const float*)d_in[26];
    const float* ct3_b   = (const float*)d_in[27];
    const float* ct4_w   = (const float*)d_in[28];
    const float* ct4_b   = (const float*)d_in[29];
    const float* ct5_w   = (const float*)d_in[30];
    const float* ct5_b   = (const float*)d_in[31];

    float *h, *hn, *xz, *xi, *dbc, *delta, *y, *t1, *sc, *attw, *pooled, *part;
    float *c1, *c2, *c3, *c4;
    cudaGetSymbolAddress((void**)&h, g_h);
    cudaGetSymbolAddress((void**)&hn, g_hn);
    cudaGetSymbolAddress((void**)&xz, g_xz);
    cudaGetSymbolAddress((void**)&xi, g_xi);
    cudaGetSymbolAddress((void**)&dbc, g_dbc);
    cudaGetSymbolAddress((void**)&delta, g_delta);
    cudaGetSymbolAddress((void**)&y, g_y);
    cudaGetSymbolAddress((void**)&t1, g_t1);
    cudaGetSymbolAddress((void**)&sc, g_s);
    cudaGetSymbolAddress((void**)&attw, g_attw);
    cudaGetSymbolAddress((void**)&pooled, g_pooled);
    cudaGetSymbolAddress((void**)&part, g_part);
    cudaGetSymbolAddress((void**)&c1, g_c1);
    cudaGetSymbolAddress((void**)&c2, g_c2);
    cudaGetSymbolAddress((void**)&c3, g_c3);
    cudaGetSymbolAddress((void**)&c4, g_c4);

    // ---- stage 0: h = gelu(x@W_fc1 + b) + posemb   (64x64 tiles, 256 CTAs)
    {
        dim3 grid(DM / 64, L / 64, 1);
        sgemm64_k<<<grid, 256>>>(L, DM, 1024, x, 1024, W_fc1, DM, h, DM,
                                 1, b_fc1, coords, W_pos, b_pos);
    }

    // ---- mamba layers
    for (int l = 0; l < 2; l++) {
        const float* inw  = in_w  + (size_t)l * DM * 2 * DI;
        const float* cw   = conv_w + (size_t)l * DI * 4;
        const float* cb   = conv_b + (size_t)l * DI;
        const float* xw   = x_w   + (size_t)l * DI * 64;
        const float* dtw  = dt_w  + (size_t)l * DTR * DI;
        const float* dtb  = dt_b  + (size_t)l * DI;
        const float* al   = A_log + (size_t)l * DI * DS;
        const float* Dl   = Dp    + (size_t)l * DI;
        const float* ow   = out_w + (size_t)l * DI * DM;
        const float* rw   = rms_w + (size_t)l * DM;

        rms_k<<<L, 128>>>(h, rw, hn);

        { // xz = hn @ in_w : [2048,512]x[512,2048]
            dim3 grid(2 * DI / 128, L / 128);
            sgemm128_k<<<grid, 256>>>(L, 2 * DI, DM, hn, DM, inw, 2 * DI, xz, 2 * DI,
                                      0, nullptr, nullptr, nullptr, nullptr);
        }

        conv_silu_k<<<(L * DI) / 256, 256>>>(xz, cw, cb, xi);

        { // dbc = xi @ xw : [2048,1024]x[1024,64], split-K 8 -> partials
            dim3 grid(1, L / 64, 8);
            sgemm64_k<<<grid, 256>>>(L, 64, DI, xi, DI, xw, 64, part, 64,
                                     0, nullptr, nullptr, nullptr, nullptr);
            reduce_k<<<(L * 64) / 256, 256>>>(part, dbc, L * 64, 64, 8, 0, nullptr);
        }

        { // delta = softplus(dt @ dtw + dtb) : A = dbc[:, :32] (lda=64)
            dim3 grid(DI / 128, L / 128);
            sgemm128_k<<<grid, 256>>>(L, DI, DTR, dbc, 64, dtw, DI, delta, DI,
                                      3, dtb, nullptr, nullptr, nullptr);
        }

        scan_k<<<DI / 8, 128>>>(delta, xi, dbc, xz, al, Dl, y);

        { // h += y @ ow : [2048,1024]x[1024,512]
            dim3 grid(DM / 64, L / 64, 1);
            sgemm64_k<<<grid, 256>>>(L, DM, DI, y, DI, ow, DM, h, DM,
                                     2, nullptr, nullptr, nullptr, nullptr);
        }
    }

    // ---- LayerNorm
    ln_k<<<L, 128>>>(h, ln_w, ln_b, hn);

    // ---- attention: t1 = tanh(hn@Wa1+ba1), split-K 4
    {
        dim3 grid(128 / 64, L / 64, 4);
        sgemm64_k<<<grid, 256>>>(L, 128, DM, hn, DM, Wa1, 128, part, 128,
                                 0, nullptr, nullptr, nullptr, nullptr);
        reduce_k<<<(L * 128) / 256, 256>>>(part, t1, L * 128, 128, 4, 4, ba1);
    }
    score_k<<<L / 8, 256>>>(t1, Wa2, ba2, sc);
    softmax_k<<<1, 1024>>>(sc, attw);
    pool_k<<<2, 256>>>(attw, hn, pooled);

    // ---- ConvTranspose2d stack
    convt_k<<<(256 * 16 + 255) / 256, 256>>>(pooled, ct1_w, ct1_b, c1,
                                             512, 256, 1, 4, 1, 0, 1, 256 * 16);
    convt_k<<<(128 * 256 + 255) / 256, 256>>>(c1, ct2_w, ct2_b, c2,
                                              256, 128, 4, 16, 4, 0, 1, 128 * 256);
    convt_k<<<(64 * 1024 + 255) / 256, 256>>>(c2, ct3_w, ct3_b, c3,
                                              128, 64, 16, 32, 2, 1, 1, 64 * 1024);
    convt_k<<<(32 * 4096 + 255) / 256, 256>>>(c3, ct4_w, ct4_b, c4,
                                              64, 32, 32, 64, 2, 1, 1, 32 * 4096);
    convt_k<<<(11 * 16384 + 255) / 256, 256>>>(c4, ct5_w, ct5_b, (float*)d_out,
                                               32, 11, 64, 128, 2, 1, 0, 11 * 16384);
}

// round 2
// speedup vs baseline: 1.3120x; 1.3120x over previous
#include <cuda_runtime.h>
#include <cuda_bf16.h>
#include <math.h>

// ---------------------------------------------------------------------------
// MambaMIL_2D forward, fp32 SIMT with packed f32x2 FMA (sm_103a FFMA2).
// L=2048, D_MODEL=512, D_INNER=1024, D_STATE=16, DT_RANK=32, N_LAYERS=2.
// ---------------------------------------------------------------------------

#define L 2048
#define DM 512
#define DI 1024
#define DS 16
#define DTR 32

typedef unsigned long long u64;

// ------------------------------- scratch ----------------------------------
__device__ float g_h   [L * DM];
__device__ float g_hn  [L * DM];
__device__ float g_xz  [L * 2 * DI];
__device__ float g_xi  [L * DI];
__device__ float g_dbc [L * 64];
__device__ float g_delta[L * DI];
__device__ float g_y   [L * DI];
__device__ float g_t1  [L * 128];
__device__ float g_s   [L];
__device__ float g_attw[L];
__device__ float g_pooled[DM];
__device__ float g_part[2 * 1024 * 1024];   // split-K / pooling partials
__device__ float g_c1[256 * 16];
__device__ float g_c2[128 * 256];
__device__ float g_c3[64 * 1024];
__device__ float g_c4[32 * 4096];

// ------------------------------ math helpers ------------------------------
__device__ __forceinline__ float geluf(float x) {
    return 0.5f * x * (1.f + erff(x * 0.70710678118654752f));
}
__device__ __forceinline__ float softplusf(float x) {
    return (x > 20.f) ? x : log1pf(__expf(x));
}
__device__ __forceinline__ float siluf(float x) {
    return x / (1.f + __expf(-x));
}
__device__ __forceinline__ float ex2f(float x) {
    float r; asm("ex2.approx.ftz.f32 %0, %1;" : "=f"(r) : "f"(x)); return r;
}
__device__ __forceinline__ u64 dup2(float x) {
    u64 r; asm("mov.b64 %0, {%1, %1};" : "=l"(r) : "f"(x)); return r;
}
__device__ __forceinline__ void fma2(u64& d, u64 a, u64 b) {
    asm("fma.rn.f32x2 %0, %1, %2, %0;" : "+l"(d) : "l"(a), "l"(b));
}

// epilogues: 0 none, 1 gelu+bias+posemb, 2 residual, 3 bias+softplus
__device__ __forceinline__ float apply_epi(float v, int row, int col, int ldc,
                                           const float* C, int epi,
                                           const float* bias, const float* aux0,
                                           const float* aux1, const float* aux2) {
    switch (epi) {
        case 1:
            v += bias[col];
            v = geluf(v);
            v += aux0[row * 2 + 0] * aux1[col] + aux0[row * 2 + 1] * aux1[512 + col] + aux2[col];
            return v;
        case 2: return v + C[(size_t)row * ldc + col];
        case 3: return softplusf(v + bias[col]);
        default: return v;
    }
}

// ------------------------ SGEMM 128x128, BK=16, FFMA2 ----------------------
// 256 thr, 8x8/thr as 2x2 quadrants of 4x4; acc row-paired for f32x2.
// Requires M%128==0, N%128==0, K%16==0.
__global__ __launch_bounds__(256, 2) void sgemm128_k(
    int M, int N, int K,
    const float* __restrict__ A, int lda,
    const float* __restrict__ B, int ldb,
    float* __restrict__ C, int ldc,
    int epi, const float* __restrict__ bias)
{
    __shared__ float As[16][132];
    __shared__ float Bs[16][128];
    int tid = threadIdx.x;
    int bm = blockIdx.y, bn = blockIdx.x;

    int aRow = tid >> 1;            // 0..127
    int aCol = (tid & 1) * 8;       // 0 or 8
    int bRow = tid >> 5;            // 0..7
    int bCol = (tid & 31) * 4;      // 0..124
    int tr = tid >> 4;              // 0..15
    int tc = tid & 15;              // 0..15

    const float* Ap = A + (size_t)(bm * 128 + aRow) * lda + aCol;
    const float* Bp = B + (size_t)bRow * ldb + bn * 128 + bCol;

    u64 accp[4][8];
#pragma unroll
    for (int i = 0; i < 4; i++)
#pragma unroll
        for (int j = 0; j < 8; j++) accp[i][j] = 0ull;

    for (int k0 = 0; k0 < K; k0 += 16) {
        float4 a0 = *(const float4*)(Ap + k0);
        float4 a1 = *(const float4*)(Ap + k0 + 4);
        float4 b0 = *(const float4*)(Bp + (size_t)k0 * ldb);
        float4 b1 = *(const float4*)(Bp + (size_t)(k0 + 8) * ldb);
        As[aCol + 0][aRow] = a0.x; As[aCol + 1][aRow] = a0.y;
        As[aCol + 2][aRow] = a0.z; As[aCol + 3][aRow] = a0.w;
        As[aCol + 4][aRow] = a1.x; As[aCol + 5][aRow] = a1.y;
        As[aCol + 6][aRow] = a1.z; As[aCol + 7][aRow] = a1.w;
        *(float4*)&Bs[bRow][bCol] = b0;
        *(float4*)&Bs[bRow + 8][bCol] = b1;
        __syncthreads();
#pragma unroll
        for (int kk = 0; kk < 16; kk++) {
            float4 ra0 = *(const float4*)&As[kk][tr * 4];
            float4 ra1 = *(const float4*)&As[kk][tr * 4 + 64];
            float4 rb0 = *(const float4*)&Bs[kk][tc * 4];
            float4 rb1 = *(const float4*)&Bs[kk][tc * 4 + 64];
            u64 rap[4];
            rap[0] = *(const u64*)&ra0.x;
            rap[1] = *(const u64*)&ra0.z;
            rap[2] = *(const u64*)&ra1.x;
            rap[3] = *(const u64*)&ra1.z;
            u64 rbd[8];
            rbd[0] = dup2(rb0.x); rbd[1] = dup2(rb0.y);
            rbd[2] = dup2(rb0.z); rbd[3] = dup2(rb0.w);
            rbd[4] = dup2(rb1.x); rbd[5] = dup2(rb1.y);
            rbd[6] = dup2(rb1.z); rbd[7] = dup2(rb1.w);
#pragma unroll
            for (int i = 0; i < 4; i++)
#pragma unroll
                for (int j = 0; j < 8; j++) fma2(accp[i][j], rap[i], rbd[j]);
        }
        __syncthreads();
    }

#pragma unroll
    for (int i = 0; i < 4; i++) {
        int row0 = bm * 128 + ((i < 2) ? (tr * 4 + i * 2) : (64 + tr * 4 + (i - 2) * 2));
#pragma unroll
        for (int j = 0; j < 8; j++) {
            int col = bn * 128 + ((j < 4) ? (tc * 4 + j) : (64 + tc * 4 + (j - 4)));
            float2 v = *(float2*)&accp[i][j];
            C[(size_t)row0 * ldc + col] =
                apply_epi(v.x, row0, col, ldc, C, epi, bias, nullptr, nullptr, nullptr);
            C[(size_t)(row0 + 1) * ldc + col] =
                apply_epi(v.y, row0 + 1, col, ldc, C, epi, bias, nullptr, nullptr, nullptr);
        }
    }
}

// ------------------------ SGEMM 128x64, BK=16, FFMA2 -----------------------
// 256 thr, 8x4/thr. Split-K via gridDim.z (raw partials into C + z*M*N).
// Requires M%128==0, N%64==0, (K/slices)%16==0.
__global__ __launch_bounds__(256, 2) void sgemm64_k(
    int M, int N, int K,
    const float* __restrict__ A, int lda,
    const float* __restrict__ B, int ldb,
    float* __restrict__ C, int ldc,
    int epi, const float* __restrict__ bias,
    const float* __restrict__ aux0, const float* __restrict__ aux1,
    const float* __restrict__ aux2)
{
    __shared__ float As[16][132];
    __shared__ float Bs[16][64];
    int tid = threadIdx.x;
    int bm = blockIdx.y, bn = blockIdx.x, bz = blockIdx.z;
    int slices = gridDim.z;
    int Ks = K / slices;
    int kbase = bz * Ks;

    int aRow = tid >> 1;           // 0..127
    int aCol = (tid & 1) * 8;      // 0 or 8
    int bRow = tid >> 4;           // 0..15
    int bCol = (tid & 15) * 4;     // 0..60
    int tr = tid >> 4;             // 0..15
    int tc = tid & 15;             // 0..15

    const float* Ap = A + (size_t)(bm * 128 + aRow) * lda + kbase + aCol;
    const float* Bp = B + (size_t)(kbase + bRow) * ldb + bn * 64 + bCol;

    u64 accp[4][4];
#pragma unroll
    for (int i = 0; i < 4; i++)
#pragma unroll
        for (int j = 0; j < 4; j++) accp[i][j] = 0ull;

    for (int k0 = 0; k0 < Ks; k0 += 16) {
        float4 a0 = *(const float4*)(Ap + k0);
        float4 a1 = *(const float4*)(Ap + k0 + 4);
        float4 b0 = *(const float4*)(Bp + (size_t)k0 * ldb);
        As[aCol + 0][aRow] = a0.x; As[aCol + 1][aRow] = a0.y;
        As[aCol + 2][aRow] = a0.z; As[aCol + 3][aRow] = a0.w;
        As[aCol + 4][aRow] = a1.x; As[aCol + 5][aRow] = a1.y;
        As[aCol + 6][aRow] = a1.z; As[aCol + 7][aRow] = a1.w;
        *(float4*)&Bs[bRow][bCol] = b0;
        __syncthreads();
#pragma unroll
        for (int kk = 0; kk < 16; kk++) {
            float4 ra0 = *(const float4*)&As[kk][tr * 4];
            float4 ra1 = *(const float4*)&As[kk][tr * 4 + 64];
            float4 rb0 = *(const float4*)&Bs[kk][tc * 4];
            u64 rap[4];
            rap[0] = *(const u64*)&ra0.x;
            rap[1] = *(const u64*)&ra0.z;
            rap[2] = *(const u64*)&ra1.x;
            rap[3] = *(const u64*)&ra1.z;
            u64 rbd[4];
            rbd[0] = dup2(rb0.x); rbd[1] = dup2(rb0.y);
            rbd[2] = dup2(rb0.z); rbd[3] = dup2(rb0.w);
#pragma unroll
            for (int i = 0; i < 4; i++)
#pragma unroll
                for (int j = 0; j < 4; j++) fma2(accp[i][j], rap[i], rbd[j]);
        }
        __syncthreads();
    }

    if (slices == 1) {
#pragma unroll
        for (int i = 0; i < 4; i++) {
            int row0 = bm * 128 + ((i < 2) ? (tr * 4 + i * 2) : (64 + tr * 4 + (i - 2) * 2));
#pragma unroll
            for (int j = 0; j < 4; j++) {
                int col = bn * 64 + tc * 4 + j;
                float2 v = *(float2*)&accp[i][j];
                C[(size_t)row0 * ldc + col] =
                    apply_epi(v.x, row0, col, ldc, C, epi, bias, aux0, aux1, aux2);
                C[(size_t)(row0 + 1) * ldc + col] =
                    apply_epi(v.y, row0 + 1, col, ldc, C, epi, bias, aux0, aux1, aux2);
            }
        }
    } else {
        float* Cp = C + (size_t)bz * M * N;
#pragma unroll
        for (int i = 0; i < 4; i++) {
            int row0 = bm * 128 + ((i < 2) ? (tr * 4 + i * 2) : (64 + tr * 4 + (i - 2) * 2));
#pragma unroll
            for (int j = 0; j < 4; j++) {
                int col = bn * 64 + tc * 4 + j;
                float2 v = *(float2*)&accp[i][j];
                Cp[(size_t)row0 * N + col] = v.x;
                Cp[(size_t)(row0 + 1) * N + col] = v.y;
            }
        }
    }
}

// reduce split-K partials (+optional tanh+bias epilogue, epi=4)
__global__ void reduce_k(const float* __restrict__ part, float* __restrict__ out,
                         int MN, int N, int slices, int epi, const float* __restrict__ bias)
{
    int idx = blockIdx.x * blockDim.x + threadIdx.x;
    if (idx >= MN) return;
    float v = 0.f;
    for (int s = 0; s < slices; s++) v += part[(size_t)s * MN + idx];
    if (epi == 4) v = tanhf(v + bias[idx % N]);
    out[idx] = v;
}

// ------------------------------- RMSNorm -----------------------------------
__global__ __launch_bounds__(128) void rms_k(const float* __restrict__ h,
                                             const float* __restrict__ w,
                                             float* __restrict__ out)
{
    int t = blockIdx.x, tid = threadIdx.x;
    float v[4]; float ss = 0.f;
#pragma unroll
    for (int i = 0; i < 4; i++) {
        v[i] = h[(size_t)t * DM + tid + i * 128];
        ss += v[i] * v[i];
    }
#pragma unroll
    for (int off = 16; off > 0; off >>= 1) ss += __shfl_xor_sync(0xffffffffu, ss, off);
    __shared__ float sm[4];
    if ((tid & 31) == 0) sm[tid >> 5] = ss;
    __syncthreads();
    float tot = sm[0] + sm[1] + sm[2] + sm[3];
    float r = rsqrtf(tot / (float)DM + 1e-5f);
#pragma unroll
    for (int i = 0; i < 4; i++) {
        int c = tid + i * 128;
        out[(size_t)t * DM + c] = v[i] * r * w[c];
    }
}

// ------------------------------- LayerNorm ---------------------------------
__global__ __launch_bounds__(128) void ln_k(const float* __restrict__ h,
                                            const float* __restrict__ w,
                                            const float* __restrict__ b,
                                            float* __restrict__ out)
{
    int t = blockIdx.x, tid = threadIdx.x;
    float v[4]; float s1 = 0.f, s2 = 0.f;
#pragma unroll
    for (int i = 0; i < 4; i++) {
        v[i] = h[(size_t)t * DM + tid + i * 128];
        s1 += v[i]; s2 += v[i] * v[i];
    }
#pragma unroll
    for (int off = 16; off > 0; off >>= 1) {
        s1 += __shfl_xor_sync(0xffffffffu, s1, off);
        s2 += __shfl_xor_sync(0xffffffffu, s2, off);
    }
    __shared__ float a1[4], a2[4];
    if ((tid & 31) == 0) { a1[tid >> 5] = s1; a2[tid >> 5] = s2; }
    __syncthreads();
    s1 = a1[0] + a1[1] + a1[2] + a1[3];
    s2 = a2[0] + a2[1] + a2[2] + a2[3];
    float mean = s1 / (float)DM;
    float var = s2 / (float)DM - mean * mean;
    float r = rsqrtf(var + 1e-5f);
#pragma unroll
    for (int i = 0; i < 4; i++) {
        int c = tid + i * 128;
        out[(size_t)t * DM + c] = (v[i] - mean) * r * w[c] + b[c];
    }
}

// --------------------------- depthwise conv + silu -------------------------
__global__ __launch_bounds__(256) void conv_silu_k(const float* __restrict__ xz,
                                                   const float* __restrict__ cw,
                                                   const float* __restrict__ cb,
                                                   float* __restrict__ xi)
{
    int idx = blockIdx.x * 256 + threadIdx.x;   // L*DI threads
    int t = idx >> 10, d = idx & 1023;
    float w0 = cw[d * 4 + 0], w1 = cw[d * 4 + 1], w2 = cw[d * 4 + 2], w3 = cw[d * 4 + 3];
    float acc = cb[d];
    if (t >= 3) acc = fmaf(xz[(size_t)(t - 3) * 2048 + d], w0, acc);
    if (t >= 2) acc = fmaf(xz[(size_t)(t - 2) * 2048 + d], w1, acc);
    if (t >= 1) acc = fmaf(xz[(size_t)(t - 1) * 2048 + d], w2, acc);
    acc = fmaf(xz[(size_t)t * 2048 + d], w3, acc);
    xi[idx] = siluf(acc);
}

// ------------------------------ selective scan ------------------------------
// block = 128 thr = 8 d-channels x 16 states. Shuffle-free: the serial loop
// stores h*C into smem; the n-reduction happens per 64-step chunk in parallel.
__global__ __launch_bounds__(128) void scan_k(
    const float* __restrict__ delta, const float* __restrict__ xi,
    const float* __restrict__ dbc, const float* __restrict__ xz,
    const float* __restrict__ alog, const float* __restrict__ Dp,
    float* __restrict__ y)
{
    __shared__ float sd[64][8], sx[64][8], sz[64][8];
    __shared__ float sBC[64][32];
    __shared__ float sp[64][8][16];
    __shared__ float sDv[8];
    int tid = threadIdx.x;
    int d0 = blockIdx.x * 8;
    int dloc = tid >> 4;
    int n = tid & 15;
    int d = d0 + dloc;
    // a_t = exp(delta * A) = exp2(delta * A * log2e)
    float AdnL2 = -__expf(alog[d * DS + n]) * 1.4426950408889634f;
    if (tid < 8) sDv[tid] = Dp[d0 + tid];
    float h = 0.f;

    for (int t0 = 0; t0 < L; t0 += 64) {
#pragma unroll
        for (int i = 0; i < 4; i++) {
            int e = tid + i * 128; int r = e >> 3, c = e & 7;
            sd[r][c] = delta[(size_t)(t0 + r) * DI + d0 + c];
            sx[r][c] = xi[(size_t)(t0 + r) * DI + d0 + c];
            sz[r][c] = xz[(size_t)(t0 + r) * 2048 + DI + d0 + c];
        }
#pragma unroll
        for (int i = 0; i < 16; i++) {
            int e = tid + i * 128; int r = e >> 5, c = e & 31;
            sBC[r][c] = dbc[(size_t)(t0 + r) * 64 + 32 + c];
        }
        __syncthreads();
#pragma unroll 4
        for (int tt = 0; tt < 64; tt++) {
            float dl = sd[tt][dloc];
            float xv = sx[tt][dloc];
            float a = ex2f(dl * AdnL2);
            float bx = dl * xv * sBC[tt][n];
            h = fmaf(a, h, bx);
            sp[tt][dloc][n] = h * sBC[tt][16 + n];
        }
        __syncthreads();
#pragma unroll
        for (int i = 0; i < 4; i++) {
            int e = tid + i * 128; int r = e >> 3, c = e & 7;
            float s = 0.f;
#pragma unroll
            for (int nn = 0; nn < 16; nn++) s += sp[r][c][nn];
            float zz = sz[r][c];
            y[(size_t)(t0 + r) * DI + d0 + c] = (s + sx[r][c] * sDv[c]) * siluf(zz);
        }
        __syncthreads();
    }
}

// -------------------------- attention score / softmax / pool ---------------
__global__ __launch_bounds__(256) void score_k(const float* __restrict__ t1,
                                               const float* __restrict__ Wa2,
                                               const float* __restrict__ ba2,
                                               float* __restrict__ s)
{
    int gw = (blockIdx.x * 256 + threadIdx.x) >> 5;
    int lane = threadIdx.x & 31;
    const float* row = t1 + (size_t)gw * 128;
    float acc = 0.f;
#pragma unroll
    for (int i = 0; i < 4; i++) acc = fmaf(row[lane + i * 32], Wa2[lane + i * 32], acc);
#pragma unroll
    for (int off = 16; off > 0; off >>= 1) acc += __shfl_xor_sync(0xffffffffu, acc, off);
    if (lane == 0) s[gw] = acc + ba2[0];
}

__global__ __launch_bounds__(1024) void softmax_k(const float* __restrict__ s,
                                                  float* __restrict__ w)
{
    int tid = threadIdx.x;
    __shared__ float red[32];
    __shared__ float bres;
    float a = s[tid], b = s[tid + 1024];
    float m = fmaxf(a, b);
#pragma unroll
    for (int off = 16; off > 0; off >>= 1) m = fmaxf(m, __shfl_xor_sync(0xffffffffu, m, off));
    if ((tid & 31) == 0) red[tid >> 5] = m;
    __syncthreads();
    if (tid < 32) {
        float x = red[tid];
#pragma unroll
        for (int off = 16; off > 0; off >>= 1) x = fmaxf(x, __shfl_xor_sync(0xffffffffu, x, off));
        if (tid == 0) bres = x;
    }
    __syncthreads();
    float M = bres;
    float ea = __expf(a - M), eb = __expf(b - M);
    float ss = ea + eb;
#pragma unroll
    for (int off = 16; off > 0; off >>= 1) ss += __shfl_xor_sync(0xffffffffu, ss, off);
    __syncthreads();
    if ((tid & 31) == 0) red[tid >> 5] = ss;
    __syncthreads();
    if (tid < 32) {
        float x = red[tid];
#pragma unroll
        for (int off = 16; off > 0; off >>= 1) x += __shfl_xor_sync(0xffffffffu, x, off);
        if (tid == 0) bres = x;
    }
    __syncthreads();
    float inv = 1.f / bres;
    w[tid] = ea * inv;
    w[tid + 1024] = eb * inv;
}

__global__ __launch_bounds__(512) void pool_part_k(const float* __restrict__ attw,
                                                   const float* __restrict__ hn,
                                                   float* __restrict__ part)
{
    int b = blockIdx.x;                // 16 t-slices
    int c = threadIdx.x;               // 512 channels
    float acc = 0.f;
    int t0 = b * 128;
#pragma unroll 8
    for (int t = t0; t < t0 + 128; t++) acc = fmaf(attw[t], hn[(size_t)t * DM + c], acc);
    part[b * DM + c] = acc;
}

__global__ __launch_bounds__(512) void pool_red_k(const float* __restrict__ part,
                                                  float* __restrict__ pooled)
{
    int c = threadIdx.x;
    float acc = 0.f;
#pragma unroll
    for (int s = 0; s < 16; s++) acc += part[s * DM + c];
    pooled[c] = acc;
}

// ---------------------------- ConvTranspose2d ------------------------------
__global__ void convt_k(const float* __restrict__ in, const float* __restrict__ w,
                        const float* __restrict__ b, float* __restrict__ out,
                        int Cin, int Cout, int Hin, int Hout, int S, int P,
                        int do_relu, int total)
{
    int idx = blockIdx.x * blockDim.x + threadIdx.x;
    if (idx >= total) return;
    int hw = Hout * Hout;
    int co = idx / hw;
    int r = idx % hw;
    int oy = r / Hout, ox = r % Hout;
    float acc = b[co];
    for (int ky = 0; ky < 4; ky++) {
        int ry = oy + P - ky;
        if (ry < 0 || (ry % S)) continue;
        int iy = ry / S;
        if (iy >= Hin) continue;
        for (int kx = 0; kx < 4; kx++) {
            int rx = ox + P - kx;
            if (rx < 0 || (rx % S)) continue;
            int ix = rx / S;
            if (ix >= Hin) continue;
            const float* wp = w + co * 16 + ky * 4 + kx;
            const float* ip = in + iy * Hin + ix;
            float ps = 0.f;
            for (int ci = 0; ci < Cin; ci++)
                ps = fmaf(ip[ci * Hin * Hin], wp[(size_t)ci * Cout * 16], ps);
            acc += ps;
        }
    }
    out[idx] = do_relu ? fmaxf(acc, 0.f) : acc;
}

// ------------------------------- launcher ----------------------------------
extern "C" void kernel_launch(void* const* d_in, const int* in_sizes, int n_in,
                              void* d_out, int out_size)
{
    const float* x       = (const float*)d_in[0];
    const float* coords  = (const float*)d_in[1];
    const float* W_fc1   = (const float*)d_in[2];
    const float* b_fc1   = (const float*)d_in[3];
    const float* W_pos   = (const float*)d_in[4];
    const float* b_pos   = (const float*)d_in[5];
    const float* in_w    = (const float*)d_in[6];
    const float* conv_w  = (const float*)d_in[7];
    const float* conv_b  = (const float*)d_in[8];
    const float* x_w     = (const float*)d_in[9];
    const float* dt_w    = (const float*)d_in[10];
    const float* dt_b    = (const float*)d_in[11];
    const float* A_log   = (const float*)d_in[12];
    const float* Dp      = (const float*)d_in[13];
    const float* out_w   = (const float*)d_in[14];
    const float* rms_w   = (const float*)d_in[15];
    const float* ln_w    = (const float*)d_in[16];
    const float* ln_b    = (const float*)d_in[17];
    const float* Wa1     = (const float*)d_in[18];
    const float* ba1     = (const float*)d_in[19];
    const float* Wa2     = (const float*)d_in[20];
    const float* ba2     = (const float*)d_in[21];
    const float* ct1_w   = (const float*)d_in[22];
    const float* ct1_b   = (const float*)d_in[23];
    const float* ct2_w   = (const float*)d_in[24];
    const float* ct2_b   = (const float*)d_in[25];
    const float* ct3_w   = (const float*)d_in[26];
    const float* ct3_b   = (const float*)d_in[27];
    const float* ct4_w   = (const float*)d_in[28];
    const float* ct4_b   = (const float*)d_in[29];
    const float* ct5_w   = (const float*)d_in[30];
    const float* ct5_b   = (const float*)d_in[31];

    float *h, *hn, *xz, *xi, *dbc, *delta, *y, *t1, *sc, *attw, *pooled, *part;
    float *c1, *c2, *c3, *c4;
    cudaGetSymbolAddress((void**)&h, g_h);
    cudaGetSymbolAddress((void**)&hn, g_hn);
    cudaGetSymbolAddress((void**)&xz, g_xz);
    cudaGetSymbolAddress((void**)&xi, g_xi);
    cudaGetSymbolAddress((void**)&dbc, g_dbc);
    cudaGetSymbolAddress((void**)&delta, g_delta);
    cudaGetSymbolAddress((void**)&y, g_y);
    cudaGetSymbolAddress((void**)&t1, g_t1);
    cudaGetSymbolAddress((void**)&sc, g_s);
    cudaGetSymbolAddress((void**)&attw, g_attw);
    cudaGetSymbolAddress((void**)&pooled, g_pooled);
    cudaGetSymbolAddress((void**)&part, g_part);
    cudaGetSymbolAddress((void**)&c1, g_c1);
    cudaGetSymbolAddress((void**)&c2, g_c2);
    cudaGetSymbolAddress((void**)&c3, g_c3);
    cudaGetSymbolAddress((void**)&c4, g_c4);

    // ---- stage 0: h = gelu(x@W_fc1 + b) + posemb : [2048,1024]x[1024,512]
    {
        dim3 grid(DM / 64, L / 128, 1);
        sgemm64_k<<<grid, 256>>>(L, DM, 1024, x, 1024, W_fc1, DM, h, DM,
                                 1, b_fc1, coords, W_pos, b_pos);
    }

    // ---- mamba layers
    for (int l = 0; l < 2; l++) {
        const float* inw  = in_w  + (size_t)l * DM * 2 * DI;
        const float* cw   = conv_w + (size_t)l * DI * 4;
        const float* cb   = conv_b + (size_t)l * DI;
        const float* xw   = x_w   + (size_t)l * DI * 64;
        const float* dtw  = dt_w  + (size_t)l * DTR * DI;
        const float* dtb  = dt_b  + (size_t)l * DI;
        const float* al   = A_log + (size_t)l * DI * DS;
        const float* Dl   = Dp    + (size_t)l * DI;
        const float* ow   = out_w + (size_t)l * DI * DM;
        const float* rw   = rms_w + (size_t)l * DM;

        rms_k<<<L, 128>>>(h, rw, hn);

        { // xz = hn @ in_w : [2048,512]x[512,2048]
            dim3 grid(2 * DI / 128, L / 128);
            sgemm128_k<<<grid, 256>>>(L, 2 * DI, DM, hn, DM, inw, 2 * DI, xz, 2 * DI,
                                      0, nullptr);
        }

        conv_silu_k<<<(L * DI) / 256, 256>>>(xz, cw, cb, xi);

        { // dbc = xi @ xw : [2048,1024]x[1024,64], split-K 8
            dim3 grid(1, L / 128, 8);
            sgemm64_k<<<grid, 256>>>(L, 64, DI, xi, DI, xw, 64, part, 64,
                                     0, nullptr, nullptr, nullptr, nullptr);
            reduce_k<<<(L * 64) / 256, 256>>>(part, dbc, L * 64, 64, 8, 0, nullptr);
        }

        { // delta = softplus(dt @ dtw + dtb), dt = dbc[:, :32] (lda=64)
            dim3 grid(DI / 128, L / 128);
            sgemm128_k<<<grid, 256>>>(L, DI, DTR, dbc, 64, dtw, DI, delta, DI,
                                      3, dtb);
        }

        scan_k<<<DI / 8, 128>>>(delta, xi, dbc, xz, al, Dl, y);

        { // h += y @ ow : [2048,1024]x[1024,512]
            dim3 grid(DM / 64, L / 128, 1);
            sgemm64_k<<<grid, 256>>>(L, DM, DI, y, DI, ow, DM, h, DM,
                                     2, nullptr, nullptr, nullptr, nullptr);
        }
    }

    // ---- LayerNorm
    ln_k<<<L, 128>>>(h, ln_w, ln_b, hn);

    // ---- attention: t1 = tanh(hn@Wa1+ba1) : split-K 4
    {
        dim3 grid(128 / 64, L / 128, 4);
        sgemm64_k<<<grid, 256>>>(L, 128, DM, hn, DM, Wa1, 128, part, 128,
                                 0, nullptr, nullptr, nullptr, nullptr);
        reduce_k<<<(L * 128) / 256, 256>>>(part, t1, L * 128, 128, 4, 4, ba1);
    }
    score_k<<<L / 8, 256>>>(t1, Wa2, ba2, sc);
    softmax_k<<<1, 1024>>>(sc, attw);
    pool_part_k<<<16, 512>>>(attw, hn, part);
    pool_red_k<<<1, 512>>>(part, pooled);

    // ---- ConvTranspose2d stack
    convt_k<<<(256 * 16 + 255) / 256, 256>>>(pooled, ct1_w, ct1_b, c1,
                                             512, 256, 1, 4, 1, 0, 1, 256 * 16);
    convt_k<<<(128 * 256 + 255) / 256, 256>>>(c1, ct2_w, ct2_b, c2,
                                              256, 128, 4, 16, 4, 0, 1, 128 * 256);
    convt_k<<<(64 * 1024 + 255) / 256, 256>>>(c2, ct3_w, ct3_b, c3,
                                              128, 64, 16, 32, 2, 1, 1, 64 * 1024);
    convt_k<<<(32 * 4096 + 255) / 256, 256>>>(c3, ct4_w, ct4_b, c4,
                                              64, 32, 32, 64, 2, 1, 1, 32 * 4096);
    convt_k<<<(11 * 16384 + 255) / 256, 256>>>(c4, ct5_w, ct5_b, (float*)d_out,
                                               32, 11, 64, 128, 2, 1, 0, 11 * 16384);
}

// round 4
// speedup vs baseline: 1.3210x; 1.0069x over previous
#include <cuda_runtime.h>
#include <cuda_bf16.h>
#include <math.h>

// ---------------------------------------------------------------------------
// MambaMIL_2D forward. Big GEMMs on HMMA (mma.sync bf16 hi/lo split, fp32 acc)
// — portable tensor path that compiles on compute_103. Rest SIMT.
// L=2048, D_MODEL=512, D_INNER=1024, D_STATE=16, DT_RANK=32, N_LAYERS=2.
// ---------------------------------------------------------------------------

#define L 2048
#define DM 512
#define DI 1024
#define DS 16
#define DTR 32

typedef unsigned long long u64;
typedef unsigned int u32;

// ------------------------------- scratch ----------------------------------
__device__ float g_h   [L * DM];
__device__ float g_hn  [L * DM];
__device__ float g_xz  [L * 2 * DI];
__device__ float g_xi  [L * DI];
__device__ float g_dbc [L * 64];
__device__ float g_delta[L * DI];
__device__ float g_y   [L * DI];
__device__ float g_t1  [L * 128];
__device__ float g_s   [L];
__device__ float g_attw[L];
__device__ float g_pooled[DM];
__device__ float g_part[1024 * 1024];
__device__ float g_c1[256 * 16];
__device__ float g_c2[128 * 256];
__device__ float g_c3[64 * 1024];
__device__ float g_c4[32 * 4096];

// split-bf16 transposed weights [N,K]
__device__ __align__(16) __nv_bfloat16 g_wfc1h[512 * 1024], g_wfc1l[512 * 1024];
__device__ __align__(16) __nv_bfloat16 g_winh[2 * 2048 * 512], g_winl[2 * 2048 * 512];
__device__ __align__(16) __nv_bfloat16 g_wouth[2 * 512 * 1024], g_woutl[2 * 512 * 1024];
__device__ __align__(16) __nv_bfloat16 g_wa1h[128 * 512], g_wa1l[128 * 512];

// ------------------------------ math helpers ------------------------------
__device__ __forceinline__ float geluf(float x) {
    return 0.5f * x * (1.f + erff(x * 0.70710678118654752f));
}
__device__ __forceinline__ float softplusf(float x) {
    return (x > 20.f) ? x : log1pf(__expf(x));
}
__device__ __forceinline__ float siluf(float x) {
    return x / (1.f + __expf(-x));
}
__device__ __forceinline__ float ex2f(float x) {
    float r; asm("ex2.approx.ftz.f32 %0, %1;" : "=f"(r) : "f"(x)); return r;
}

// epilogues: 0 none, 1 gelu+bias+posemb, 2 residual, 3 bias+softplus, 4 bias+tanh
__device__ __forceinline__ float apply_epi(float v, int row, int col, int ldc,
                                           const float* C, int epi,
                                           const float* bias, const float* aux0,
                                           const float* aux1, const float* aux2) {
    switch (epi) {
        case 1:
            v += bias[col];
            v = geluf(v);
            v += aux0[row * 2 + 0] * aux1[col] + aux0[row * 2 + 1] * aux1[512 + col] + aux2[col];
            return v;
        case 2: return v + C[(size_t)row * ldc + col];
        case 3: return softplusf(v + bias[col]);
        case 4: return tanhf(v + bias[col]);
        default: return v;
    }
}

// --------------------------- HMMA helpers ----------------------------------
__device__ __forceinline__ u32 smem_u32(const void* p) {
    u32 a;
    asm("{ .reg .u64 t; cvta.to.shared.u64 t, %1; cvt.u32.u64 %0, t; }" : "=r"(a) : "l"(p));
    return a;
}
__device__ __forceinline__ void ldsm4(u32* r, u32 addr) {
    asm volatile("ldmatrix.sync.aligned.m8n8.x4.shared.b16 {%0,%1,%2,%3}, [%4];"
                 : "=r"(r[0]), "=r"(r[1]), "=r"(r[2]), "=r"(r[3]) : "r"(addr));
}
__device__ __forceinline__ void mma_bf16(float* c, const u32* a, const u32* b) {
    asm volatile("mma.sync.aligned.m16n8k16.row.col.f32.bf16.bf16.f32 "
                 "{%0,%1,%2,%3}, {%4,%5,%6,%7}, {%8,%9}, {%0,%1,%2,%3};"
                 : "+f"(c[0]), "+f"(c[1]), "+f"(c[2]), "+f"(c[3])
                 : "r"(a[0]), "r"(a[1]), "r"(a[2]), "r"(a[3]), "r"(b[0]), "r"(b[1]));
}
__device__ __forceinline__ void split2(float x, float y, u32& h, u32& l) {
    __nv_bfloat16 hx = __float2bfloat16_rn(x);
    __nv_bfloat16 hy = __float2bfloat16_rn(y);
    __nv_bfloat16 lx = __float2bfloat16_rn(x - __bfloat162float(hx));
    __nv_bfloat16 ly = __float2bfloat16_rn(y - __bfloat162float(hy));
    h = ((u32)__bfloat16_as_ushort(hy) << 16) | (u32)__bfloat16_as_ushort(hx);
    l = ((u32)__bfloat16_as_ushort(ly) << 16) | (u32)__bfloat16_as_ushort(lx);
}

// -------------------- weight transpose + bf16 hi/lo split -------------------
// W[K,N] fp32 -> hi/lo [N,K] bf16
__global__ void wsplit_k(const float* __restrict__ W, int K, int N,
                         __nv_bfloat16* __restrict__ hi, __nv_bfloat16* __restrict__ lo)
{
    int idx = blockIdx.x * 256 + threadIdx.x;
    if (idx >= K * N) return;
    int n = idx / K, k = idx % K;
    float v = W[(size_t)k * N + n];
    __nv_bfloat16 h = __float2bfloat16_rn(v);
    hi[idx] = h;
    lo[idx] = __float2bfloat16_rn(v - __bfloat162float(h));
}

// ------------------------ HMMA split-bf16 GEMM ------------------------------
// C[M,N] = A[M,K](fp32) * B^T, B stored [N,K] bf16 hi/lo. Tile 128x128, BK=32,
// 8 warps (4m x 2n), per-warp 32x64 via m16n8k16; 3 MMAs per product (hi/lo).
// Requires M%128==0, N%128==0, K%32==0.
#define SPAD 40   // padded k-stride (bf16 elems): conflict-free ldmatrix

__global__ void __launch_bounds__(256) hmma_gemm_k(
    int M, int N, int K,
    const float* __restrict__ A, int lda,
    const __nv_bfloat16* __restrict__ Bhi, const __nv_bfloat16* __restrict__ Blo,
    float* __restrict__ C, int ldc,
    int epi, const float* __restrict__ bias,
    const float* __restrict__ aux0, const float* __restrict__ aux1,
    const float* __restrict__ aux2)
{
    __shared__ __nv_bfloat16 sAh[128 * SPAD], sAl[128 * SPAD];
    __shared__ __nv_bfloat16 sBh[128 * SPAD], sBl[128 * SPAD];
    int tid = threadIdx.x, lane = tid & 31, wid = tid >> 5;
    int bm = blockIdx.y, bn = blockIdx.x;
    int wm = wid & 3, wn = wid >> 2;
    int NC = K / 32;

    u32 baseAh = smem_u32(sAh), baseAl = smem_u32(sAl);
    u32 baseBh = smem_u32(sBh), baseBl = smem_u32(sBl);

    float acc[2][8][4];
#pragma unroll
    for (int mt = 0; mt < 2; mt++)
#pragma unroll
        for (int nt = 0; nt < 8; nt++)
#pragma unroll
            for (int q = 0; q < 4; q++) acc[mt][nt][q] = 0.f;

    // prefetch registers
    float4 pa[4];
    uint4 pbh[2], pbl[2];

    auto gload = [&](int kc) {
#pragma unroll
        for (int i = 0; i < 4; i++) {
            int s = tid + i * 256;          // 0..1023, A: 128 rows x 8 float4
            int r = s >> 3, kq = s & 7;
            pa[i] = *(const float4*)(A + (size_t)(bm * 128 + r) * lda + kc * 32 + kq * 4);
        }
#pragma unroll
        for (int i = 0; i < 2; i++) {
            int s = tid + i * 256;          // 0..511, B: 128 rows x 4 uint4
            int r = s >> 2, kq = s & 3;
            size_t off = (size_t)(bn * 128 + r) * K + kc * 32 + kq * 8;
            pbh[i] = *(const uint4*)(Bhi + off);
            pbl[i] = *(const uint4*)(Blo + off);
        }
    };
    auto sstore = [&]() {
#pragma unroll
        for (int i = 0; i < 4; i++) {
            int s = tid + i * 256;
            int r = s >> 3, kq = s & 7;
            u32 h0, l0, h1, l1;
            split2(pa[i].x, pa[i].y, h0, l0);
            split2(pa[i].z, pa[i].w, h1, l1);
            *(uint2*)&sAh[r * SPAD + kq * 4] = make_uint2(h0, h1);
            *(uint2*)&sAl[r * SPAD + kq * 4] = make_uint2(l0, l1);
        }
#pragma unroll
        for (int i = 0; i < 2; i++) {
            int s = tid + i * 256;
            int r = s >> 2, kq = s & 3;
            *(uint4*)&sBh[r * SPAD + kq * 8] = pbh[i];
            *(uint4*)&sBl[r * SPAD + kq * 8] = pbl[i];
        }
    };

    gload(0);
    for (int kc = 0; kc < NC; kc++) {
        sstore();
        __syncthreads();
        if (kc + 1 < NC) gload(kc + 1);
#pragma unroll
        for (int ks = 0; ks < 2; ks++) {
            // A fragments: row = wm*32 + mt*16 + (mat&1)*8 + lrow ; k = ks*16 + (mat>>1)*8
            u32 ah[2][4], al[2][4];
#pragma unroll
            for (int mt = 0; mt < 2; mt++) {
                int row = wm * 32 + mt * 16 + ((lane >> 3) & 1) * 8 + (lane & 7);
                int kcol = ks * 16 + (lane >> 4) * 8;
                u32 off = (u32)(row * SPAD + kcol) * 2;
                ldsm4(ah[mt], baseAh + off);
                ldsm4(al[mt], baseAl + off);
            }
            // B fragments: n = wn*64 + p*16 + (mat>>1)*8 + lrow ; k = ks*16 + (mat&1)*8
            u32 bh[8][2], bl[8][2];
#pragma unroll
            for (int p = 0; p < 4; p++) {
                int n = wn * 64 + p * 16 + (lane >> 4) * 8 + (lane & 7);
                int kcol = ks * 16 + ((lane >> 3) & 1) * 8;
                u32 off = (u32)(n * SPAD + kcol) * 2;
                u32 r4[4];
                ldsm4(r4, baseBh + off);
                bh[p * 2][0] = r4[0]; bh[p * 2][1] = r4[1];
                bh[p * 2 + 1][0] = r4[2]; bh[p * 2 + 1][1] = r4[3];
                ldsm4(r4, baseBl + off);
                bl[p * 2][0] = r4[0]; bl[p * 2][1] = r4[1];
                bl[p * 2 + 1][0] = r4[2]; bl[p * 2 + 1][1] = r4[3];
            }
#pragma unroll
            for (int mt = 0; mt < 2; mt++)
#pragma unroll
                for (int nt = 0; nt < 8; nt++) {
                    mma_bf16(acc[mt][nt], ah[mt], bh[nt]);
                    mma_bf16(acc[mt][nt], ah[mt], bl[nt]);
                    mma_bf16(acc[mt][nt], al[mt], bh[nt]);
                }
        }
        __syncthreads();
    }

    // epilogue: acc quad mapping of m16n8k16
#pragma unroll
    for (int mt = 0; mt < 2; mt++) {
        int row0 = bm * 128 + wm * 32 + mt * 16 + (lane >> 2);
#pragma unroll
        for (int nt = 0; nt < 8; nt++) {
            int col = bn * 128 + wn * 64 + nt * 8 + (lane & 3) * 2;
            float v0 = apply_epi(acc[mt][nt][0], row0, col, ldc, C, epi, bias, aux0, aux1, aux2);
            float v1 = apply_epi(acc[mt][nt][1], row0, col + 1, ldc, C, epi, bias, aux0, aux1, aux2);
            C[(size_t)row0 * ldc + col] = v0;
            C[(size_t)row0 * ldc + col + 1] = v1;
            int row1 = row0 + 8;
            float v2 = apply_epi(acc[mt][nt][2], row1, col, ldc, C, epi, bias, aux0, aux1, aux2);
            float v3 = apply_epi(acc[mt][nt][3], row1, col + 1, ldc, C, epi, bias, aux0, aux1, aux2);
            C[(size_t)row1 * ldc + col] = v2;
            C[(size_t)row1 * ldc + col + 1] = v3;
        }
    }
}

// ------------------------ SIMT SGEMM 128x64 (small GEMMs) ------------------
__global__ __launch_bounds__(256, 2) void sgemm64_k(
    int M, int N, int K,
    const float* __restrict__ A, int lda,
    const float* __restrict__ B, int ldb,
    float* __restrict__ C, int ldc,
    int epi, const float* __restrict__ bias)
{
    __shared__ float As[16][132];
    __shared__ float Bs[16][64];
    int tid = threadIdx.x;
    int bm = blockIdx.y, bn = blockIdx.x, bz = blockIdx.z;
    int slices = gridDim.z;
    int Ks = K / slices;
    int kbase = bz * Ks;

    int aRow = tid >> 1;
    int aCol = (tid & 1) * 8;
    int bRow = tid >> 4;
    int bCol = (tid & 15) * 4;
    int tr = tid >> 4;
    int tc = tid & 15;

    const float* Ap = A + (size_t)(bm * 128 + aRow) * lda + kbase + aCol;
    const float* Bp = B + (size_t)(kbase + bRow) * ldb + bn * 64 + bCol;

    float acc[8][4];
#pragma unroll
    for (int i = 0; i < 8; i++)
#pragma unroll
        for (int j = 0; j < 4; j++) acc[i][j] = 0.f;

    for (int k0 = 0; k0 < Ks; k0 += 16) {
        float4 a0 = *(const float4*)(Ap + k0);
        float4 a1 = *(const float4*)(Ap + k0 + 4);
        float4 b0 = *(const float4*)(Bp + (size_t)k0 * ldb);
        As[aCol + 0][aRow] = a0.x; As[aCol + 1][aRow] = a0.y;
        As[aCol + 2][aRow] = a0.z; As[aCol + 3][aRow] = a0.w;
        As[aCol + 4][aRow] = a1.x; As[aCol + 5][aRow] = a1.y;
        As[aCol + 6][aRow] = a1.z; As[aCol + 7][aRow] = a1.w;
        *(float4*)&Bs[bRow][bCol] = b0;
        __syncthreads();
#pragma unroll
        for (int kk = 0; kk < 16; kk++) {
            float4 ra0 = *(const float4*)&As[kk][tr * 4];
            float4 ra1 = *(const float4*)&As[kk][tr * 4 + 64];
            float4 rb0 = *(const float4*)&Bs[kk][tc * 4];
            float ra[8] = {ra0.x, ra0.y, ra0.z, ra0.w, ra1.x, ra1.y, ra1.z, ra1.w};
            float rb[4] = {rb0.x, rb0.y, rb0.z, rb0.w};
#pragma unroll
            for (int i = 0; i < 8; i++)
#pragma unroll
                for (int j = 0; j < 4; j++)
                    acc[i][j] = fmaf(ra[i], rb[j], acc[i][j]);
        }
        __syncthreads();
    }

    if (slices == 1) {
#pragma unroll
        for (int i = 0; i < 8; i++) {
            int row = bm * 128 + ((i < 4) ? (tr * 4 + i) : (64 + tr * 4 + i - 4));
#pragma unroll
            for (int j = 0; j < 4; j++) {
                int col = bn * 64 + tc * 4 + j;
                C[(size_t)row * ldc + col] =
                    apply_epi(acc[i][j], row, col, ldc, C, epi, bias, nullptr, nullptr, nullptr);
            }
        }
    } else {
        float* Cp = C + (size_t)bz * M * N;
#pragma unroll
        for (int i = 0; i < 8; i++) {
            int row = bm * 128 + ((i < 4) ? (tr * 4 + i) : (64 + tr * 4 + i - 4));
#pragma unroll
            for (int j = 0; j < 4; j++) {
                int col = bn * 64 + tc * 4 + j;
                Cp[(size_t)row * N + col] = acc[i][j];
            }
        }
    }
}

__global__ void reduce_k(const float* __restrict__ part, float* __restrict__ out,
                         int MN, int slices)
{
    int idx = blockIdx.x * blockDim.x + threadIdx.x;
    if (idx >= MN) return;
    float v = 0.f;
    for (int s = 0; s < slices; s++) v += part[(size_t)s * MN + idx];
    out[idx] = v;
}

// --------------------------- delta GEMM (K=32) ------------------------------
__global__ __launch_bounds__(256) void delta_k(
    const float* __restrict__ dbc, const float* __restrict__ dtw,
    const float* __restrict__ dtb, float* __restrict__ delta)
{
    __shared__ float As[128][33];
    __shared__ float Bs[32][128];
    int tid = threadIdx.x;
    int bm = blockIdx.y, bn = blockIdx.x;
#pragma unroll
    for (int i = 0; i < 16; i++) {
        int e = tid + i * 256;
        int r = e >> 5, c = e & 31;
        As[r][c] = dbc[(size_t)(bm * 128 + r) * 64 + c];
    }
#pragma unroll
    for (int i = 0; i < 16; i++) {
        int e = tid + i * 256;
        int r = e >> 7, c = e & 127;
        Bs[r][c] = dtw[(size_t)r * DI + bn * 128 + c];
    }
    __syncthreads();
    int tr = tid >> 4, tc = tid & 15;
    float acc[8][8];
#pragma unroll
    for (int i = 0; i < 8; i++)
#pragma unroll
        for (int j = 0; j < 8; j++) acc[i][j] = 0.f;
#pragma unroll
    for (int k = 0; k < 32; k++) {
        float ra[8], rb[8];
#pragma unroll
        for (int i = 0; i < 8; i++) ra[i] = As[tr * 8 + i][k];
#pragma unroll
        for (int j = 0; j < 8; j++) rb[j] = Bs[k][tc * 8 + j];
#pragma unroll
        for (int i = 0; i < 8; i++)
#pragma unroll
            for (int j = 0; j < 8; j++) acc[i][j] = fmaf(ra[i], rb[j], acc[i][j]);
    }
#pragma unroll
    for (int i = 0; i < 8; i++) {
        int row = bm * 128 + tr * 8 + i;
#pragma unroll
        for (int j = 0; j < 8; j++) {
            int col = bn * 128 + tc * 8 + j;
            delta[(size_t)row * DI + col] = softplusf(acc[i][j] + dtb[col]);
        }
    }
}

// ------------------------------- RMSNorm -----------------------------------
__global__ __launch_bounds__(128) void rms_k(const float* __restrict__ h,
                                             const float* __restrict__ w,
                                             float* __restrict__ out)
{
    int t = blockIdx.x, tid = threadIdx.x;
    float v[4]; float ss = 0.f;
#pragma unroll
    for (int i = 0; i < 4; i++) {
        v[i] = h[(size_t)t * DM + tid + i * 128];
        ss += v[i] * v[i];
    }
#pragma unroll
    for (int off = 16; off > 0; off >>= 1) ss += __shfl_xor_sync(0xffffffffu, ss, off);
    __shared__ float sm[4];
    if ((tid & 31) == 0) sm[tid >> 5] = ss;
    __syncthreads();
    float tot = sm[0] + sm[1] + sm[2] + sm[3];
    float r = rsqrtf(tot / (float)DM + 1e-5f);
#pragma unroll
    for (int i = 0; i < 4; i++) {
        int c = tid + i * 128;
        out[(size_t)t * DM + c] = v[i] * r * w[c];
    }
}

// ------------------------------- LayerNorm ---------------------------------
__global__ __launch_bounds__(128) void ln_k(const float* __restrict__ h,
                                            const float* __restrict__ w,
                                            const float* __restrict__ b,
                                            float* __restrict__ out)
{
    int t = blockIdx.x, tid = threadIdx.x;
    float v[4]; float s1 = 0.f, s2 = 0.f;
#pragma unroll
    for (int i = 0; i < 4; i++) {
        v[i] = h[(size_t)t * DM + tid + i * 128];
        s1 += v[i]; s2 += v[i] * v[i];
    }
#pragma unroll
    for (int off = 16; off > 0; off >>= 1) {
        s1 += __shfl_xor_sync(0xffffffffu, s1, off);
        s2 += __shfl_xor_sync(0xffffffffu, s2, off);
    }
    __shared__ float a1[4], a2[4];
    if ((tid & 31) == 0) { a1[tid >> 5] = s1; a2[tid >> 5] = s2; }
    __syncthreads();
    s1 = a1[0] + a1[1] + a1[2] + a1[3];
    s2 = a2[0] + a2[1] + a2[2] + a2[3];
    float mean = s1 / (float)DM;
    float var = s2 / (float)DM - mean * mean;
    float r = rsqrtf(var + 1e-5f);
#pragma unroll
    for (int i = 0; i < 4; i++) {
        int c = tid + i * 128;
        out[(size_t)t * DM + c] = (v[i] - mean) * r * w[c] + b[c];
    }
}

// --------------------------- depthwise conv + silu -------------------------
__global__ __launch_bounds__(256) void conv_silu_k(const float* __restrict__ xz,
                                                   const float* __restrict__ cw,
                                                   const float* __restrict__ cb,
                                                   float* __restrict__ xi)
{
    int idx = blockIdx.x * 256 + threadIdx.x;
    int t = idx >> 10, d = idx & 1023;
    float w0 = cw[d * 4 + 0], w1 = cw[d * 4 + 1], w2 = cw[d * 4 + 2], w3 = cw[d * 4 + 3];
    float acc = cb[d];
    if (t >= 3) acc = fmaf(xz[(size_t)(t - 3) * 2048 + d], w0, acc);
    if (t >= 2) acc = fmaf(xz[(size_t)(t - 2) * 2048 + d], w1, acc);
    if (t >= 1) acc = fmaf(xz[(size_t)(t - 1) * 2048 + d], w2, acc);
    acc = fmaf(xz[(size_t)t * 2048 + d], w3, acc);
    xi[idx] = siluf(acc);
}

// ------------------------------ selective scan ------------------------------
__global__ __launch_bounds__(128) void scan_k(
    const float* __restrict__ delta, const float* __restrict__ xi,
    const float* __restrict__ dbc, const float* __restrict__ xz,
    const float* __restrict__ alog, const float* __restrict__ Dp,
    float* __restrict__ y)
{
    __shared__ float sd[64][8], sx[64][8], sz[64][8];
    __shared__ float sBC[64][32];
    __shared__ float sp[64][8][16];
    __shared__ float sDv[8];
    int tid = threadIdx.x;
    int d0 = blockIdx.x * 8;
    int dloc = tid >> 4;
    int n = tid & 15;
    int d = d0 + dloc;
    float AdnL2 = -__expf(alog[d * DS + n]) * 1.4426950408889634f;
    if (tid < 8) sDv[tid] = Dp[d0 + tid];
    float h = 0.f;

    for (int t0 = 0; t0 < L; t0 += 64) {
#pragma unroll
        for (int i = 0; i < 4; i++) {
            int e = tid + i * 128; int r = e >> 3, c = e & 7;
            sd[r][c] = delta[(size_t)(t0 + r) * DI + d0 + c];
            sx[r][c] = xi[(size_t)(t0 + r) * DI + d0 + c];
            sz[r][c] = xz[(size_t)(t0 + r) * 2048 + DI + d0 + c];
        }
#pragma unroll
        for (int i = 0; i < 16; i++) {
            int e = tid + i * 128; int r = e >> 5, c = e & 31;
            sBC[r][c] = dbc[(size_t)(t0 + r) * 64 + 32 + c];
        }
        __syncthreads();
#pragma unroll 4
        for (int tt = 0; tt < 64; tt++) {
            float dl = sd[tt][dloc];
            float xv = sx[tt][dloc];
            float a = ex2f(dl * AdnL2);
            float bx = dl * xv * sBC[tt][n];
            h = fmaf(a, h, bx);
            sp[tt][dloc][n] = h * sBC[tt][16 + n];
        }
        __syncthreads();
#pragma unroll
        for (int i = 0; i < 4; i++) {
            int e = tid + i * 128; int r = e >> 3, c = e & 7;
            float s = 0.f;
#pragma unroll
            for (int nn = 0; nn < 16; nn++) s += sp[r][c][nn];
            float zz = sz[r][c];
            y[(size_t)(t0 + r) * DI + d0 + c] = (s + sx[r][c] * sDv[c]) * siluf(zz);
        }
        __syncthreads();
    }
}

// -------------------------- attention score / softmax / pool ---------------
__global__ __launch_bounds__(256) void score_k(const float* __restrict__ t1,
                                               const float* __restrict__ Wa2,
                                               const float* __restrict__ ba2,
                                               float* __restrict__ s)
{
    int gw = (blockIdx.x * 256 + threadIdx.x) >> 5;
    int lane = threadIdx.x & 31;
    const float* row = t1 + (size_t)gw * 128;
    float acc = 0.f;
#pragma unroll
    for (int i = 0; i < 4; i++) acc = fmaf(row[lane + i * 32], Wa2[lane + i * 32], acc);
#pragma unroll
    for (int off = 16; off > 0; off >>= 1) acc += __shfl_xor_sync(0xffffffffu, acc, off);
    if (lane == 0) s[gw] = acc + ba2[0];
}

__global__ __launch_bounds__(1024) void softmax_k(const float* __restrict__ s,
                                                  float* __restrict__ w)
{
    int tid = threadIdx.x;
    __shared__ float red[32];
    __shared__ float bres;
    float a = s[tid], b = s[tid + 1024];
    float m = fmaxf(a, b);
#pragma unroll
    for (int off = 16; off > 0; off >>= 1) m = fmaxf(m, __shfl_xor_sync(0xffffffffu, m, off));
    if ((tid & 31) == 0) red[tid >> 5] = m;
    __syncthreads();
    if (tid < 32) {
        float x = red[tid];
#pragma unroll
        for (int off = 16; off > 0; off >>= 1) x = fmaxf(x, __shfl_xor_sync(0xffffffffu, x, off));
        if (tid == 0) bres = x;
    }
    __syncthreads();
    float M = bres;
    float ea = __expf(a - M), eb = __expf(b - M);
    float ss = ea + eb;
#pragma unroll
    for (int off = 16; off > 0; off >>= 1) ss += __shfl_xor_sync(0xffffffffu, ss, off);
    __syncthreads();
    if ((tid & 31) == 0) red[tid >> 5] = ss;
    __syncthreads();
    if (tid < 32) {
        float x = red[tid];
#pragma unroll
        for (int off = 16; off > 0; off >>= 1) x += __shfl_xor_sync(0xffffffffu, x, off);
        if (tid == 0) bres = x;
    }
    __syncthreads();
    float inv = 1.f / bres;
    w[tid] = ea * inv;
    w[tid + 1024] = eb * inv;
}

__global__ __launch_bounds__(512) void pool_part_k(const float* __restrict__ attw,
                                                   const float* __restrict__ hn,
                                                   float* __restrict__ part)
{
    int b = blockIdx.x;
    int c = threadIdx.x;
    float acc = 0.f;
    int t0 = b * 128;
#pragma unroll 8
    for (int t = t0; t < t0 + 128; t++) acc = fmaf(attw[t], hn[(size_t)t * DM + c], acc);
    part[b * DM + c] = acc;
}

__global__ __launch_bounds__(512) void pool_red_k(const float* __restrict__ part,
                                                  float* __restrict__ pooled)
{
    int c = threadIdx.x;
    float acc = 0.f;
#pragma unroll
    for (int s = 0; s < 16; s++) acc += part[s * DM + c];
    pooled[c] = acc;
}

// ---------------------------- ConvTranspose2d ------------------------------
__global__ void convt_k(const float* __restrict__ in, const float* __restrict__ w,
                        const float* __restrict__ b, float* __restrict__ out,
                        int Cin, int Cout, int Hin, int Hout, int S, int P,
                        int do_relu, int total)
{
    int idx = blockIdx.x * blockDim.x + threadIdx.x;
    if (idx >= total) return;
    int hw = Hout * Hout;
    int co = idx / hw;
    int r = idx % hw;
    int oy = r / Hout, ox = r % Hout;
    float acc = b[co];
    for (int ky = 0; ky < 4; ky++) {
        int ry = oy + P - ky;
        if (ry < 0 || (ry % S)) continue;
        int iy = ry / S;
        if (iy >= Hin) continue;
        for (int kx = 0; kx < 4; kx++) {
            int rx = ox + P - kx;
            if (rx < 0 || (rx % S)) continue;
            int ix = rx / S;
            if (ix >= Hin) continue;
            const float* wp = w + co * 16 + ky * 4 + kx;
            const float* ip = in + iy * Hin + ix;
            float ps = 0.f;
            for (int ci = 0; ci < Cin; ci++)
                ps = fmaf(ip[ci * Hin * Hin], wp[(size_t)ci * Cout * 16], ps);
            acc += ps;
        }
    }
    out[idx] = do_relu ? fmaxf(acc, 0.f) : acc;
}

// ------------------------------- launcher ----------------------------------
extern "C" void kernel_launch(void* const* d_in, const int* in_sizes, int n_in,
                              void* d_out, int out_size)
{
    const float* x       = (const float*)d_in[0];
    const float* coords  = (const float*)d_in[1];
    const float* W_fc1   = (const float*)d_in[2];
    const float* b_fc1   = (const float*)d_in[3];
    const float* W_pos   = (const float*)d_in[4];
    const float* b_pos   = (const float*)d_in[5];
    const float* in_w    = (const float*)d_in[6];
    const float* conv_w  = (const float*)d_in[7];
    const float* conv_b  = (const float*)d_in[8];
    const float* x_w     = (const float*)d_in[9];
    const float* dt_w    = (const float*)d_in[10];
    const float* dt_b    = (const float*)d_in[11];
    const float* A_log   = (const float*)d_in[12];
    const float* Dp      = (const float*)d_in[13];
    const float* out_w   = (const float*)d_in[14];
    const float* rms_w   = (const float*)d_in[15];
    const float* ln_w    = (const float*)d_in[16];
    const float* ln_b    = (const float*)d_in[17];
    const float* Wa1     = (const float*)d_in[18];
    const float* ba1     = (const float*)d_in[19];
    const float* Wa2     = (const float*)d_in[20];
    const float* ba2     = (const float*)d_in[21];
    const float* ct1_w   = (const float*)d_in[22];
    const float* ct1_b   = (const float*)d_in[23];
    const float* ct2_w   = (const float*)d_in[24];
    const float* ct2_b   = (const float*)d_in[25];
    const float* ct3_w   = (const float*)d_in[26];
    const float* ct3_b   = (const float*)d_in[27];
    const float* ct4_w   = (const float*)d_in[28];
    const float* ct4_b   = (const float*)d_in[29];
    const float* ct5_w   = (const float*)d_in[30];
    const float* ct5_b   = (const float*)d_in[31];

    float *h, *hn, *xz, *xi, *dbc, *delta, *y, *t1, *sc, *attw, *pooled, *part;
    float *c1, *c2, *c3, *c4;
    __nv_bfloat16 *wfc1h, *wfc1l, *winh, *winl, *wouth, *woutl, *wa1h, *wa1l;
    cudaGetSymbolAddress((void**)&h, g_h);
    cudaGetSymbolAddress((void**)&hn, g_hn);
    cudaGetSymbolAddress((void**)&xz, g_xz);
    cudaGetSymbolAddress((void**)&xi, g_xi);
    cudaGetSymbolAddress((void**)&dbc, g_dbc);
    cudaGetSymbolAddress((void**)&delta, g_delta);
    cudaGetSymbolAddress((void**)&y, g_y);
    cudaGetSymbolAddress((void**)&t1, g_t1);
    cudaGetSymbolAddress((void**)&sc, g_s);
    cudaGetSymbolAddress((void**)&attw, g_attw);
    cudaGetSymbolAddress((void**)&pooled, g_pooled);
    cudaGetSymbolAddress((void**)&part, g_part);
    cudaGetSymbolAddress((void**)&c1, g_c1);
    cudaGetSymbolAddress((void**)&c2, g_c2);
    cudaGetSymbolAddress((void**)&c3, g_c3);
    cudaGetSymbolAddress((void**)&c4, g_c4);
    cudaGetSymbolAddress((void**)&wfc1h, g_wfc1h);
    cudaGetSymbolAddress((void**)&wfc1l, g_wfc1l);
    cudaGetSymbolAddress((void**)&winh, g_winh);
    cudaGetSymbolAddress((void**)&winl, g_winl);
    cudaGetSymbolAddress((void**)&wouth, g_wouth);
    cudaGetSymbolAddress((void**)&woutl, g_woutl);
    cudaGetSymbolAddress((void**)&wa1h, g_wa1h);
    cudaGetSymbolAddress((void**)&wa1l, g_wa1l);

    // ---- weight transpose + split (bf16 hi/lo, [N,K]) ----
    wsplit_k<<<(1024 * 512 + 255) / 256, 256>>>(W_fc1, 1024, 512, wfc1h, wfc1l);
    for (int l = 0; l < 2; l++) {
        wsplit_k<<<(512 * 2048 + 255) / 256, 256>>>(in_w + (size_t)l * 512 * 2048, 512, 2048,
                                                    winh + (size_t)l * 2048 * 512,
                                                    winl + (size_t)l * 2048 * 512);
        wsplit_k<<<(1024 * 512 + 255) / 256, 256>>>(out_w + (size_t)l * 1024 * 512, 1024, 512,
                                                    wouth + (size_t)l * 512 * 1024,
                                                    woutl + (size_t)l * 512 * 1024);
    }
    wsplit_k<<<(512 * 128 + 255) / 256, 256>>>(Wa1, 512, 128, wa1h, wa1l);

    // ---- stage 0: h = gelu(x@W_fc1 + b) + posemb ----
    {
        dim3 g(4, 16);
        hmma_gemm_k<<<g, 256>>>(L, DM, 1024, x, 1024, wfc1h, wfc1l, h, DM,
                                1, b_fc1, coords, W_pos, b_pos);
    }

    // ---- mamba layers ----
    for (int l = 0; l < 2; l++) {
        const float* cw  = conv_w + (size_t)l * DI * 4;
        const float* cb  = conv_b + (size_t)l * DI;
        const float* xw  = x_w   + (size_t)l * DI * 64;
        const float* dtw = dt_w  + (size_t)l * DTR * DI;
        const float* dtb = dt_b  + (size_t)l * DI;
        const float* al  = A_log + (size_t)l * DI * DS;
        const float* Dl  = Dp    + (size_t)l * DI;
        const float* rw  = rms_w + (size_t)l * DM;

        rms_k<<<L, 128>>>(h, rw, hn);

        { // xz = hn @ in_w
            dim3 g(16, 16);
            hmma_gemm_k<<<g, 256>>>(L, 2 * DI, DM, hn, DM,
                                    winh + (size_t)l * 2048 * 512,
                                    winl + (size_t)l * 2048 * 512,
                                    xz, 2 * DI, 0, nullptr, nullptr, nullptr, nullptr);
        }

        conv_silu_k<<<(L * DI) / 256, 256>>>(xz, cw, cb, xi);

        { // dbc = xi @ xw (split-K 8)
            dim3 g(1, L / 128, 8);
            sgemm64_k<<<g, 256>>>(L, 64, DI, xi, DI, xw, 64, part, 64, 0, nullptr);
            reduce_k<<<(L * 64) / 256, 256>>>(part, dbc, L * 64, 8);
        }

        { // delta = softplus(dbc[:, :32] @ dtw + dtb)
            dim3 g(DI / 128, L / 128);
            delta_k<<<g, 256>>>(dbc, dtw, dtb, delta);
        }

        scan_k<<<DI / 8, 128>>>(delta, xi, dbc, xz, al, Dl, y);

        { // h += y @ out_w
            dim3 g(4, 16);
            hmma_gemm_k<<<g, 256>>>(L, DM, DI, y, DI,
                                    wouth + (size_t)l * 512 * 1024,
                                    woutl + (size_t)l * 512 * 1024,
                                    h, DM, 2, nullptr, nullptr, nullptr, nullptr);
        }
    }

    // ---- LayerNorm ----
    ln_k<<<L, 128>>>(h, ln_w, ln_b, hn);

    // ---- attention: t1 = tanh(hn@Wa1+ba1) ----
    {
        dim3 g(1, 16);
        hmma_gemm_k<<<g, 256>>>(L, 128, DM, hn, DM, wa1h, wa1l, t1, 128,
                                4, ba1, nullptr, nullptr, nullptr);
    }
    score_k<<<L / 8, 256>>>(t1, Wa2, ba2, sc);
    softmax_k<<<1, 1024>>>(sc, attw);
    pool_part_k<<<16, 512>>>(attw, hn, part);
    pool_red_k<<<1, 512>>>(part, pooled);

    // ---- ConvTranspose2d stack ----
    convt_k<<<(256 * 16 + 255) / 256, 256>>>(pooled, ct1_w, ct1_b, c1,
                                             512, 256, 1, 4, 1, 0, 1, 256 * 16);
    convt_k<<<(128 * 256 + 255) / 256, 256>>>(c1, ct2_w, ct2_b, c2,
                                              256, 128, 4, 16, 4, 0, 1, 128 * 256);
    convt_k<<<(64 * 1024 + 255) / 256, 256>>>(c2, ct3_w, ct3_b, c3,
                                              128, 64, 16, 32, 2, 1, 1, 64 * 1024);
    convt_k<<<(32 * 4096 + 255) / 256, 256>>>(c3, ct4_w, ct4_b, c4,
                                              64, 32, 32, 64, 2, 1, 1, 32 * 4096);
    convt_k<<<(11 * 16384 + 255) / 256, 256>>>(c4, ct5_w, ct5_b, (float*)d_out,
                                               32, 11, 64, 128, 2, 1, 0, 11 * 16384);
}

// round 6
// speedup vs baseline: 1.3733x; 1.0396x over previous
#include <cuda_runtime.h>
#include <cuda_bf16.h>
#include <math.h>

// ---------------------------------------------------------------------------
// MambaMIL_2D forward. Big GEMMs on HMMA (mma.sync bf16 hi/lo split, fp32 acc),
// split-K for chip fill, double-buffered smem. Rest SIMT.
// ---------------------------------------------------------------------------

#define L 2048
#define DM 512
#define DI 1024
#define DS 16
#define DTR 32

typedef unsigned long long u64;
typedef unsigned int u32;

// ------------------------------- scratch ----------------------------------
__device__ float g_h   [L * DM];
__device__ float g_hn  [L * DM];
__device__ float g_xz  [L * 2 * DI];
__device__ float g_xi  [L * DI];
__device__ float g_dbc [L * 64];
__device__ float g_delta[L * DI];
__device__ float g_y   [L * DI];
__device__ float g_t1  [L * 128];
__device__ float g_s   [L];
__device__ float g_attw[L];
__device__ float g_pooled[DM];
__device__ float g_part[4 * 1024 * 1024];   // split-K partials (16MB)
__device__ float g_c1[256 * 16];
__device__ float g_c2[128 * 256];
__device__ float g_c3[64 * 1024];
__device__ float g_c4[32 * 4096];

// split-bf16 transposed weights [N,K]
__device__ __align__(16) __nv_bfloat16 g_wfc1h[512 * 1024], g_wfc1l[512 * 1024];
__device__ __align__(16) __nv_bfloat16 g_winh[2 * 2048 * 512], g_winl[2 * 2048 * 512];
__device__ __align__(16) __nv_bfloat16 g_wouth[2 * 512 * 1024], g_woutl[2 * 512 * 1024];
__device__ __align__(16) __nv_bfloat16 g_wa1h[128 * 512], g_wa1l[128 * 512];

// ------------------------------ math helpers ------------------------------
__device__ __forceinline__ float geluf(float x) {
    return 0.5f * x * (1.f + erff(x * 0.70710678118654752f));
}
__device__ __forceinline__ float softplusf(float x) {
    return (x > 20.f) ? x : log1pf(__expf(x));
}
__device__ __forceinline__ float siluf(float x) {
    return x / (1.f + __expf(-x));
}
__device__ __forceinline__ float ex2f(float x) {
    float r; asm("ex2.approx.ftz.f32 %0, %1;" : "=f"(r) : "f"(x)); return r;
}

// epilogues: 0 none, 1 gelu+bias+posemb, 2 residual-add, 3 bias+softplus, 4 bias+tanh
__device__ __forceinline__ float apply_epi(float v, int row, int col, int ldc,
                                           const float* C, int epi,
                                           const float* bias, const float* aux0,
                                           const float* aux1, const float* aux2) {
    switch (epi) {
        case 1:
            v += bias[col];
            v = geluf(v);
            v += aux0[row * 2 + 0] * aux1[col] + aux0[row * 2 + 1] * aux1[512 + col] + aux2[col];
            return v;
        case 2: return v + C[(size_t)row * ldc + col];
        case 3: return softplusf(v + bias[col]);
        case 4: return tanhf(v + bias[col]);
        default: return v;
    }
}

// --------------------------- HMMA helpers ----------------------------------
__device__ __forceinline__ u32 smem_u32(const void* p) {
    u32 a;
    asm("{ .reg .u64 t; cvta.to.shared.u64 t, %1; cvt.u32.u64 %0, t; }" : "=r"(a) : "l"(p));
    return a;
}
__device__ __forceinline__ void ldsm4(u32* r, u32 addr) {
    asm volatile("ldmatrix.sync.aligned.m8n8.x4.shared.b16 {%0,%1,%2,%3}, [%4];"
                 : "=r"(r[0]), "=r"(r[1]), "=r"(r[2]), "=r"(r[3]) : "r"(addr));
}
__device__ __forceinline__ void mma_bf16(float* c, const u32* a, const u32* b) {
    asm volatile("mma.sync.aligned.m16n8k16.row.col.f32.bf16.bf16.f32 "
                 "{%0,%1,%2,%3}, {%4,%5,%6,%7}, {%8,%9}, {%0,%1,%2,%3};"
                 : "+f"(c[0]), "+f"(c[1]), "+f"(c[2]), "+f"(c[3])
                 : "r"(a[0]), "r"(a[1]), "r"(a[2]), "r"(a[3]), "r"(b[0]), "r"(b[1]));
}
__device__ __forceinline__ void split2(float x, float y, u32& h, u32& l) {
    __nv_bfloat16 hx = __float2bfloat16_rn(x);
    __nv_bfloat16 hy = __float2bfloat16_rn(y);
    __nv_bfloat16 lx = __float2bfloat16_rn(x - __bfloat162float(hx));
    __nv_bfloat16 ly = __float2bfloat16_rn(y - __bfloat162float(hy));
    h = ((u32)__bfloat16_as_ushort(hy) << 16) | (u32)__bfloat16_as_ushort(hx);
    l = ((u32)__bfloat16_as_ushort(ly) << 16) | (u32)__bfloat16_as_ushort(lx);
}

// -------------------- weight transpose + bf16 hi/lo split -------------------
__global__ void wsplit_k(const float* __restrict__ W, int K, int N,
                         __nv_bfloat16* __restrict__ hi, __nv_bfloat16* __restrict__ lo)
{
    int idx = blockIdx.x * 256 + threadIdx.x;
    if (idx >= K * N) return;
    int n = idx / K, k = idx % K;
    float v = W[(size_t)k * N + n];
    __nv_bfloat16 h = __float2bfloat16_rn(v);
    hi[idx] = h;
    lo[idx] = __float2bfloat16_rn(v - __bfloat162float(h));
}

// ------------------------ HMMA split-bf16 GEMM ------------------------------
// C[M,N] = A[M,K](fp32)*B^T, B [N,K] bf16 hi/lo. Tile 128x128, BK=32, 8 warps,
// double-buffered dynamic smem. Split-K via gridDim.z (raw partials C+z*M*N).
#define SPAD 40
#define BUFB (4 * 128 * SPAD * 2)            // bytes per buffer (4 arrays)
#define HSMEM (2 * BUFB)                      // 81920

__global__ void __launch_bounds__(256) hmma_gemm_k(
    int M, int N, int K,
    const float* __restrict__ A, int lda,
    const __nv_bfloat16* __restrict__ Bhi, const __nv_bfloat16* __restrict__ Blo,
    float* __restrict__ C, int ldc,
    int epi, const float* __restrict__ bias,
    const float* __restrict__ aux0, const float* __restrict__ aux1,
    const float* __restrict__ aux2)
{
    extern __shared__ char dsm[];
    int tid = threadIdx.x, lane = tid & 31, wid = tid >> 5;
    int bm = blockIdx.y, bn = blockIdx.x, bz = blockIdx.z;
    int slices = gridDim.z;
    int Ks = K / slices;
    int kbase = bz * Ks;
    int wm = wid & 3, wn = wid >> 2;
    int NC = Ks / 32;

    const int AB = 128 * SPAD * 2;  // bytes per bf16 array
    u32 sb = smem_u32(dsm);

    float acc[2][8][4];
#pragma unroll
    for (int mt = 0; mt < 2; mt++)
#pragma unroll
        for (int nt = 0; nt < 8; nt++)
#pragma unroll
            for (int q = 0; q < 4; q++) acc[mt][nt][q] = 0.f;

    float4 pa[4];
    uint4 pbh[2], pbl[2];

    auto gload = [&](int kc) {
#pragma unroll
        for (int i = 0; i < 4; i++) {
            int s = tid + i * 256;
            int r = s >> 3, kq = s & 7;
            pa[i] = *(const float4*)(A + (size_t)(bm * 128 + r) * lda + kbase + kc * 32 + kq * 4);
        }
#pragma unroll
        for (int i = 0; i < 2; i++) {
            int s = tid + i * 256;
            int r = s >> 2, kq = s & 3;
            size_t off = (size_t)(bn * 128 + r) * K + kbase + kc * 32 + kq * 8;
            pbh[i] = *(const uint4*)(Bhi + off);
            pbl[i] = *(const uint4*)(Blo + off);
        }
    };
    auto sstore = [&](int buf) {
        char* bufp = dsm + buf * BUFB;
#pragma unroll
        for (int i = 0; i < 4; i++) {
            int s = tid + i * 256;
            int r = s >> 3, kq = s & 7;
            u32 h0, l0, h1, l1;
            split2(pa[i].x, pa[i].y, h0, l0);
            split2(pa[i].z, pa[i].w, h1, l1);
            *(uint2*)(bufp + (r * SPAD + kq * 4) * 2)      = make_uint2(h0, h1);
            *(uint2*)(bufp + AB + (r * SPAD + kq * 4) * 2) = make_uint2(l0, l1);
        }
#pragma unroll
        for (int i = 0; i < 2; i++) {
            int s = tid + i * 256;
            int r = s >> 2, kq = s & 3;
            *(uint4*)(bufp + 2 * AB + (r * SPAD + kq * 8) * 2) = pbh[i];
            *(uint4*)(bufp + 3 * AB + (r * SPAD + kq * 8) * 2) = pbl[i];
        }
    };

    gload(0);
    sstore(0);
    __syncthreads();

    for (int kc = 0; kc < NC; kc++) {
        int buf = kc & 1;
        if (kc + 1 < NC) gload(kc + 1);
        u32 bAh = sb + buf * BUFB;
        u32 bAl = bAh + AB;
        u32 bBh = bAh + 2 * AB;
        u32 bBl = bAh + 3 * AB;
#pragma unroll
        for (int ks = 0; ks < 2; ks++) {
            u32 ah[2][4], al[2][4];
#pragma unroll
            for (int mt = 0; mt < 2; mt++) {
                int row = wm * 32 + mt * 16 + ((lane >> 3) & 1) * 8 + (lane & 7);
                int kcol = ks * 16 + (lane >> 4) * 8;
                u32 off = (u32)(row * SPAD + kcol) * 2;
                ldsm4(ah[mt], bAh + off);
                ldsm4(al[mt], bAl + off);
            }
            u32 bh[8][2], bl[8][2];
#pragma unroll
            for (int p = 0; p < 4; p++) {
                int n = wn * 64 + p * 16 + (lane >> 4) * 8 + (lane & 7);
                int kcol = ks * 16 + ((lane >> 3) & 1) * 8;
                u32 off = (u32)(n * SPAD + kcol) * 2;
                u32 r4[4];
                ldsm4(r4, bBh + off);
                bh[p * 2][0] = r4[0]; bh[p * 2][1] = r4[1];
                bh[p * 2 + 1][0] = r4[2]; bh[p * 2 + 1][1] = r4[3];
                ldsm4(r4, bBl + off);
                bl[p * 2][0] = r4[0]; bl[p * 2][1] = r4[1];
                bl[p * 2 + 1][0] = r4[2]; bl[p * 2 + 1][1] = r4[3];
            }
#pragma unroll
            for (int mt = 0; mt < 2; mt++)
#pragma unroll
                for (int nt = 0; nt < 8; nt++) {
                    mma_bf16(acc[mt][nt], ah[mt], bh[nt]);
                    mma_bf16(acc[mt][nt], ah[mt], bl[nt]);
                    mma_bf16(acc[mt][nt], al[mt], bh[nt]);
                }
        }
        if (kc + 1 < NC) sstore(1 - buf);
        __syncthreads();
    }

    if (slices == 1) {
#pragma unroll
        for (int mt = 0; mt < 2; mt++) {
            int row0 = bm * 128 + wm * 32 + mt * 16 + (lane >> 2);
#pragma unroll
            for (int nt = 0; nt < 8; nt++) {
                int col = bn * 128 + wn * 64 + nt * 8 + (lane & 3) * 2;
                C[(size_t)row0 * ldc + col] =
                    apply_epi(acc[mt][nt][0], row0, col, ldc, C, epi, bias, aux0, aux1, aux2);
                C[(size_t)row0 * ldc + col + 1] =
                    apply_epi(acc[mt][nt][1], row0, col + 1, ldc, C, epi, bias, aux0, aux1, aux2);
                int row1 = row0 + 8;
                C[(size_t)row1 * ldc + col] =
                    apply_epi(acc[mt][nt][2], row1, col, ldc, C, epi, bias, aux0, aux1, aux2);
                C[(size_t)row1 * ldc + col + 1] =
                    apply_epi(acc[mt][nt][3], row1, col + 1, ldc, C, epi, bias, aux0, aux1, aux2);
            }
        }
    } else {
        float* Cp = C + (size_t)bz * M * N;
#pragma unroll
        for (int mt = 0; mt < 2; mt++) {
            int row0 = bm * 128 + wm * 32 + mt * 16 + (lane >> 2);
#pragma unroll
            for (int nt = 0; nt < 8; nt++) {
                int col = bn * 128 + wn * 64 + nt * 8 + (lane & 3) * 2;
                Cp[(size_t)row0 * N + col]       = acc[mt][nt][0];
                Cp[(size_t)row0 * N + col + 1]   = acc[mt][nt][1];
                Cp[(size_t)(row0 + 8) * N + col] = acc[mt][nt][2];
                Cp[(size_t)(row0 + 8) * N + col + 1] = acc[mt][nt][3];
            }
        }
    }
}

// reduce split-K partials + full epilogue support
__global__ void reduce_k(const float* __restrict__ part, float* __restrict__ out,
                         int MN, int N, int slices, int epi,
                         const float* __restrict__ bias, const float* __restrict__ aux0,
                         const float* __restrict__ aux1, const float* __restrict__ aux2)
{
    int idx = blockIdx.x * blockDim.x + threadIdx.x;
    if (idx >= MN) return;
    float v = 0.f;
    for (int s = 0; s < slices; s++) v += part[(size_t)s * MN + idx];
    int row = idx / N, col = idx % N;
    switch (epi) {
        case 1:
            v += bias[col];
            v = geluf(v);
            v += aux0[row * 2 + 0] * aux1[col] + aux0[row * 2 + 1] * aux1[512 + col] + aux2[col];
            break;
        case 2: v += out[idx]; break;
        case 4: v = tanhf(v + bias[col]); break;
        default: break;
    }
    out[idx] = v;
}

// ------------------------ SIMT SGEMM 128x64 (dbc GEMM) ---------------------
__global__ __launch_bounds__(256, 2) void sgemm64_k(
    int M, int N, int K,
    const float* __restrict__ A, int lda,
    const float* __restrict__ B, int ldb,
    float* __restrict__ C)
{
    __shared__ float As[16][132];
    __shared__ float Bs[16][64];
    int tid = threadIdx.x;
    int bm = blockIdx.y, bn = blockIdx.x, bz = blockIdx.z;
    int slices = gridDim.z;
    int Ks = K / slices;
    int kbase = bz * Ks;

    int aRow = tid >> 1;
    int aCol = (tid & 1) * 8;
    int bRow = tid >> 4;
    int bCol = (tid & 15) * 4;
    int tr = tid >> 4;
    int tc = tid & 15;

    const float* Ap = A + (size_t)(bm * 128 + aRow) * lda + kbase + aCol;
    const float* Bp = B + (size_t)(kbase + bRow) * ldb + bn * 64 + bCol;

    float acc[8][4];
#pragma unroll
    for (int i = 0; i < 8; i++)
#pragma unroll
        for (int j = 0; j < 4; j++) acc[i][j] = 0.f;

    for (int k0 = 0; k0 < Ks; k0 += 16) {
        float4 a0 = *(const float4*)(Ap + k0);
        float4 a1 = *(const float4*)(Ap + k0 + 4);
        float4 b0 = *(const float4*)(Bp + (size_t)k0 * ldb);
        As[aCol + 0][aRow] = a0.x; As[aCol + 1][aRow] = a0.y;
        As[aCol + 2][aRow] = a0.z; As[aCol + 3][aRow] = a0.w;
        As[aCol + 4][aRow] = a1.x; As[aCol + 5][aRow] = a1.y;
        As[aCol + 6][aRow] = a1.z; As[aCol + 7][aRow] = a1.w;
        *(float4*)&Bs[bRow][bCol] = b0;
        __syncthreads();
#pragma unroll
        for (int kk = 0; kk < 16; kk++) {
            float4 ra0 = *(const float4*)&As[kk][tr * 4];
            float4 ra1 = *(const float4*)&As[kk][tr * 4 + 64];
            float4 rb0 = *(const float4*)&Bs[kk][tc * 4];
            float ra[8] = {ra0.x, ra0.y, ra0.z, ra0.w, ra1.x, ra1.y, ra1.z, ra1.w};
            float rb[4] = {rb0.x, rb0.y, rb0.z, rb0.w};
#pragma unroll
            for (int i = 0; i < 8; i++)
#pragma unroll
                for (int j = 0; j < 4; j++)
                    acc[i][j] = fmaf(ra[i], rb[j], acc[i][j]);
        }
        __syncthreads();
    }

    float* Cp = C + (size_t)bz * M * N;
#pragma unroll
    for (int i = 0; i < 8; i++) {
        int row = bm * 128 + ((i < 4) ? (tr * 4 + i) : (64 + tr * 4 + i - 4));
#pragma unroll
        for (int j = 0; j < 4; j++) {
            int col = bn * 64 + tc * 4 + j;
            Cp[(size_t)row * N + col] = acc[i][j];
        }
    }
}

// --------------------------- delta GEMM (K=32) ------------------------------
__global__ __launch_bounds__(256) void delta_k(
    const float* __restrict__ dbc, const float* __restrict__ dtw,
    const float* __restrict__ dtb, float* __restrict__ delta)
{
    __shared__ float As[128][33];
    __shared__ float Bs[32][128];
    int tid = threadIdx.x;
    int bm = blockIdx.y, bn = blockIdx.x;
#pragma unroll
    for (int i = 0; i < 16; i++) {
        int e = tid + i * 256;
        int r = e >> 5, c = e & 31;
        As[r][c] = dbc[(size_t)(bm * 128 + r) * 64 + c];
    }
#pragma unroll
    for (int i = 0; i < 16; i++) {
        int e = tid + i * 256;
        int r = e >> 7, c = e & 127;
        Bs[r][c] = dtw[(size_t)r * DI + bn * 128 + c];
    }
    __syncthreads();
    int tr = tid >> 4, tc = tid & 15;
    float acc[8][8];
#pragma unroll
    for (int i = 0; i < 8; i++)
#pragma unroll
        for (int j = 0; j < 8; j++) acc[i][j] = 0.f;
#pragma unroll
    for (int k = 0; k < 32; k++) {
        float ra[8], rb[8];
#pragma unroll
        for (int i = 0; i < 8; i++) ra[i] = As[tr * 8 + i][k];
#pragma unroll
        for (int j = 0; j < 8; j++) rb[j] = Bs[k][tc * 8 + j];
#pragma unroll
        for (int i = 0; i < 8; i++)
#pragma unroll
            for (int j = 0; j < 8; j++) acc[i][j] = fmaf(ra[i], rb[j], acc[i][j]);
    }
#pragma unroll
    for (int i = 0; i < 8; i++) {
        int row = bm * 128 + tr * 8 + i;
#pragma unroll
        for (int j = 0; j < 8; j++) {
            int col = bn * 128 + tc * 8 + j;
            delta[(size_t)row * DI + col] = softplusf(acc[i][j] + dtb[col]);
        }
    }
}

// ------------------------------- RMSNorm -----------------------------------
__global__ __launch_bounds__(128) void rms_k(const float* __restrict__ h,
                                             const float* __restrict__ w,
                                             float* __restrict__ out)
{
    int t = blockIdx.x, tid = threadIdx.x;
    float v[4]; float ss = 0.f;
#pragma unroll
    for (int i = 0; i < 4; i++) {
        v[i] = h[(size_t)t * DM + tid + i * 128];
        ss += v[i] * v[i];
    }
#pragma unroll
    for (int off = 16; off > 0; off >>= 1) ss += __shfl_xor_sync(0xffffffffu, ss, off);
    __shared__ float sm[4];
    if ((tid & 31) == 0) sm[tid >> 5] = ss;
    __syncthreads();
    float tot = sm[0] + sm[1] + sm[2] + sm[3];
    float r = rsqrtf(tot / (float)DM + 1e-5f);
#pragma unroll
    for (int i = 0; i < 4; i++) {
        int c = tid + i * 128;
        out[(size_t)t * DM + c] = v[i] * r * w[c];
    }
}

// ------------------------------- LayerNorm ---------------------------------
__global__ __launch_bounds__(128) void ln_k(const float* __restrict__ h,
                                            const float* __restrict__ w,
                                            const float* __restrict__ b,
                                            float* __restrict__ out)
{
    int t = blockIdx.x, tid = threadIdx.x;
    float v[4]; float s1 = 0.f, s2 = 0.f;
#pragma unroll
    for (int i = 0; i < 4; i++) {
        v[i] = h[(size_t)t * DM + tid + i * 128];
        s1 += v[i]; s2 += v[i] * v[i];
    }
#pragma unroll
    for (int off = 16; off > 0; off >>= 1) {
        s1 += __shfl_xor_sync(0xffffffffu, s1, off);
        s2 += __shfl_xor_sync(0xffffffffu, s2, off);
    }
    __shared__ float a1[4], a2[4];
    if ((tid & 31) == 0) { a1[tid >> 5] = s1; a2[tid >> 5] = s2; }
    __syncthreads();
    s1 = a1[0] + a1[1] + a1[2] + a1[3];
    s2 = a2[0] + a2[1] + a2[2] + a2[3];
    float mean = s1 / (float)DM;
    float var = s2 / (float)DM - mean * mean;
    float r = rsqrtf(var + 1e-5f);
#pragma unroll
    for (int i = 0; i < 4; i++) {
        int c = tid + i * 128;
        out[(size_t)t * DM + c] = (v[i] - mean) * r * w[c] + b[c];
    }
}

// --------------------------- depthwise conv + silu -------------------------
__global__ __launch_bounds__(256) void conv_silu_k(const float* __restrict__ xz,
                                                   const float* __restrict__ cw,
                                                   const float* __restrict__ cb,
                                                   float* __restrict__ xi)
{
    int idx = blockIdx.x * 256 + threadIdx.x;
    int t = idx >> 10, d = idx & 1023;
    float w0 = cw[d * 4 + 0], w1 = cw[d * 4 + 1], w2 = cw[d * 4 + 2], w3 = cw[d * 4 + 3];
    float acc = cb[d];
    if (t >= 3) acc = fmaf(xz[(size_t)(t - 3) * 2048 + d], w0, acc);
    if (t >= 2) acc = fmaf(xz[(size_t)(t - 2) * 2048 + d], w1, acc);
    if (t >= 1) acc = fmaf(xz[(size_t)(t - 1) * 2048 + d], w2, acc);
    acc = fmaf(xz[(size_t)t * 2048 + d], w3, acc);
    xi[idx] = siluf(acc);
}

// ------------------------------ selective scan ------------------------------
__global__ __launch_bounds__(128) void scan_k(
    const float* __restrict__ delta, const float* __restrict__ xi,
    const float* __restrict__ dbc, const float* __restrict__ xz,
    const float* __restrict__ alog, const float* __restrict__ Dp,
    float* __restrict__ y)
{
    __shared__ float sd[64][8], sx[64][8], sz[64][8];
    __shared__ float sBC[64][32];
    __shared__ float sp[64][8][16];
    __shared__ float sDv[8];
    int tid = threadIdx.x;
    int d0 = blockIdx.x * 8;
    int dloc = tid >> 4;
    int n = tid & 15;
    int d = d0 + dloc;
    float AdnL2 = -__expf(alog[d * DS + n]) * 1.4426950408889634f;
    if (tid < 8) sDv[tid] = Dp[d0 + tid];
    float h = 0.f;

    for (int t0 = 0; t0 < L; t0 += 64) {
#pragma unroll
        for (int i = 0; i < 4; i++) {
            int e = tid + i * 128; int r = e >> 3, c = e & 7;
            sd[r][c] = delta[(size_t)(t0 + r) * DI + d0 + c];
            sx[r][c] = xi[(size_t)(t0 + r) * DI + d0 + c];
            sz[r][c] = xz[(size_t)(t0 + r) * 2048 + DI + d0 + c];
        }
#pragma unroll
        for (int i = 0; i < 16; i++) {
            int e = tid + i * 128; int r = e >> 5, c = e & 31;
            sBC[r][c] = dbc[(size_t)(t0 + r) * 64 + 32 + c];
        }
        __syncthreads();
#pragma unroll 4
        for (int tt = 0; tt < 64; tt++) {
            float dl = sd[tt][dloc];
            float xv = sx[tt][dloc];
            float a = ex2f(dl * AdnL2);
            float bx = dl * xv * sBC[tt][n];
            h = fmaf(a, h, bx);
            sp[tt][dloc][n] = h * sBC[tt][16 + n];
        }
        __syncthreads();
#pragma unroll
        for (int i = 0; i < 4; i++) {
            int e = tid + i * 128; int r = e >> 3, c = e & 7;
            float s = 0.f;
#pragma unroll
            for (int nn = 0; nn < 16; nn++) s += sp[r][c][nn];
            float zz = sz[r][c];
            y[(size_t)(t0 + r) * DI + d0 + c] = (s + sx[r][c] * sDv[c]) * siluf(zz);
        }
        __syncthreads();
    }
}

// -------------------------- attention score / softmax / pool ---------------
__global__ __launch_bounds__(256) void score_k(const float* __restrict__ t1,
                                               const float* __restrict__ Wa2,
                                               const float* __restrict__ ba2,
                                               float* __restrict__ s)
{
    int gw = (blockIdx.x * 256 + threadIdx.x) >> 5;
    int lane = threadIdx.x & 31;
    const float* row = t1 + (size_t)gw * 128;
    float acc = 0.f;
#pragma unroll
    for (int i = 0; i < 4; i++) acc = fmaf(row[lane + i * 32], Wa2[lane + i * 32], acc);
#pragma unroll
    for (int off = 16; off > 0; off >>= 1) acc += __shfl_xor_sync(0xffffffffu, acc, off);
    if (lane == 0) s[gw] = acc + ba2[0];
}

__global__ __launch_bounds__(1024) void softmax_k(const float* __restrict__ s,
                                                  float* __restrict__ w)
{
    int tid = threadIdx.x;
    __shared__ float red[32];
    __shared__ float bres;
    float a = s[tid], b = s[tid + 1024];
    float m = fmaxf(a, b);
#pragma unroll
    for (int off = 16; off > 0; off >>= 1) m = fmaxf(m, __shfl_xor_sync(0xffffffffu, m, off));
    if ((tid & 31) == 0) red[tid >> 5] = m;
    __syncthreads();
    if (tid < 32) {
        float x = red[tid];
#pragma unroll
        for (int off = 16; off > 0; off >>= 1) x = fmaxf(x, __shfl_xor_sync(0xffffffffu, x, off));
        if (tid == 0) bres = x;
    }
    __syncthreads();
    float M = bres;
    float ea = __expf(a - M), eb = __expf(b - M);
    float ss = ea + eb;
#pragma unroll
    for (int off = 16; off > 0; off >>= 1) ss += __shfl_xor_sync(0xffffffffu, ss, off);
    __syncthreads();
    if ((tid & 31) == 0) red[tid >> 5] = ss;
    __syncthreads();
    if (tid < 32) {
        float x = red[tid];
#pragma unroll
        for (int off = 16; off > 0; off >>= 1) x += __shfl_xor_sync(0xffffffffu, x, off);
        if (tid == 0) bres = x;
    }
    __syncthreads();
    float inv = 1.f / bres;
    w[tid] = ea * inv;
    w[tid + 1024] = eb * inv;
}

__global__ __launch_bounds__(512) void pool_part_k(const float* __restrict__ attw,
                                                   const float* __restrict__ hn,
                                                   float* __restrict__ part)
{
    int b = blockIdx.x;
    int c = threadIdx.x;
    float acc = 0.f;
    int t0 = b * 128;
#pragma unroll 8
    for (int t = t0; t < t0 + 128; t++) acc = fmaf(attw[t], hn[(size_t)t * DM + c], acc);
    part[b * DM + c] = acc;
}

__global__ __launch_bounds__(512) void pool_red_k(const float* __restrict__ part,
                                                  float* __restrict__ pooled)
{
    int c = threadIdx.x;
    float acc = 0.f;
#pragma unroll
    for (int s = 0; s < 16; s++) acc += part[s * DM + c];
    pooled[c] = acc;
}

// ---------------------------- ConvTranspose2d ------------------------------
__global__ void convt_k(const float* __restrict__ in, const float* __restrict__ w,
                        const float* __restrict__ b, float* __restrict__ out,
                        int Cin, int Cout, int Hin, int Hout, int S, int P,
                        int do_relu, int total)
{
    int idx = blockIdx.x * blockDim.x + threadIdx.x;
    if (idx >= total) return;
    int hw = Hout * Hout;
    int co = idx / hw;
    int r = idx % hw;
    int oy = r / Hout, ox = r % Hout;
    float acc = b[co];
    for (int ky = 0; ky < 4; ky++) {
        int ry = oy + P - ky;
        if (ry < 0 || (ry % S)) continue;
        int iy = ry / S;
        if (iy >= Hin) continue;
        for (int kx = 0; kx < 4; kx++) {
            int rx = ox + P - kx;
            if (rx < 0 || (rx % S)) continue;
            int ix = rx / S;
            if (ix >= Hin) continue;
            const float* wp = w + co * 16 + ky * 4 + kx;
            const float* ip = in + iy * Hin + ix;
            float ps = 0.f;
            for (int ci = 0; ci < Cin; ci++)
                ps = fmaf(ip[ci * Hin * Hin], wp[(size_t)ci * Cout * 16], ps);
            acc += ps;
        }
    }
    out[idx] = do_relu ? fmaxf(acc, 0.f) : acc;
}

// ------------------------------- launcher ----------------------------------
extern "C" void kernel_launch(void* const* d_in, const int* in_sizes, int n_in,
                              void* d_out, int out_size)
{
    const float* x       = (const float*)d_in[0];
    const float* coords  = (const float*)d_in[1];
    const float* W_fc1   = (const float*)d_in[2];
    const float* b_fc1   = (const float*)d_in[3];
    const float* W_pos   = (const float*)d_in[4];
    const float* b_pos   = (const float*)d_in[5];
    const float* in_w    = (const float*)d_in[6];
    const float* conv_w  = (const float*)d_in[7];
    const float* conv_b  = (const float*)d_in[8];
    const float* x_w     = (const float*)d_in[9];
    const float* dt_w    = (const float*)d_in[10];
    const float* dt_b    = (const float*)d_in[11];
    const float* A_log   = (const float*)d_in[12];
    const float* Dp      = (const float*)d_in[13];
    const float* out_w   = (const float*)d_in[14];
    const float* rms_w   = (const float*)d_in[15];
    const float* ln_w    = (const float*)d_in[16];
    const float* ln_b    = (const float*)d_in[17];
    const float* Wa1     = (const float*)d_in[18];
    const float* ba1     = (const float*)d_in[19];
    const float* Wa2     = (const float*)d_in[20];
    const float* ba2     = (const float*)d_in[21];
    const float* ct1_w   = (const float*)d_in[22];
    const float* ct1_b   = (const float*)d_in[23];
    const float* ct2_w   = (const float*)d_in[24];
    const float* ct2_b   = (const float*)d_in[25];
    const float* ct3_w   = (const float*)d_in[26];
    const float* ct3_b   = (const float*)d_in[27];
    const float* ct4_w   = (const float*)d_in[28];
    const float* ct4_b   = (const float*)d_in[29];
    const float* ct5_w   = (const float*)d_in[30];
    const float* ct5_b   = (const float*)d_in[31];

    float *h, *hn, *xz, *xi, *dbc, *delta, *y, *t1, *sc, *attw, *pooled, *part;
    float *c1, *c2, *c3, *c4;
    __nv_bfloat16 *wfc1h, *wfc1l, *winh, *winl, *wouth, *woutl, *wa1h, *wa1l;
    cudaGetSymbolAddress((void**)&h, g_h);
    cudaGetSymbolAddress((void**)&hn, g_hn);
    cudaGetSymbolAddress((void**)&xz, g_xz);
    cudaGetSymbolAddress((void**)&xi, g_xi);
    cudaGetSymbolAddress((void**)&dbc, g_dbc);
    cudaGetSymbolAddress((void**)&delta, g_delta);
    cudaGetSymbolAddress((void**)&y, g_y);
    cudaGetSymbolAddress((void**)&t1, g_t1);
    cudaGetSymbolAddress((void**)&sc, g_s);
    cudaGetSymbolAddress((void**)&attw, g_attw);
    cudaGetSymbolAddress((void**)&pooled, g_pooled);
    cudaGetSymbolAddress((void**)&part, g_part);
    cudaGetSymbolAddress((void**)&c1, g_c1);
    cudaGetSymbolAddress((void**)&c2, g_c2);
    cudaGetSymbolAddress((void**)&c3, g_c3);
    cudaGetSymbolAddress((void**)&c4, g_c4);
    cudaGetSymbolAddress((void**)&wfc1h, g_wfc1h);
    cudaGetSymbolAddress((void**)&wfc1l, g_wfc1l);
    cudaGetSymbolAddress((void**)&winh, g_winh);
    cudaGetSymbolAddress((void**)&winl, g_winl);
    cudaGetSymbolAddress((void**)&wouth, g_wouth);
    cudaGetSymbolAddress((void**)&woutl, g_woutl);
    cudaGetSymbolAddress((void**)&wa1h, g_wa1h);
    cudaGetSymbolAddress((void**)&wa1l, g_wa1l);

    cudaFuncSetAttribute(hmma_gemm_k, cudaFuncAttributeMaxDynamicSharedMemorySize, HSMEM);

    // ---- weight splits: exactly 5 launches, then launch #6 = fc1 HMMA (ncu) --
    wsplit_k<<<(1024 * 512 + 255) / 256, 256>>>(W_fc1, 1024, 512, wfc1h, wfc1l);            // 1
    wsplit_k<<<(512 * 2048 + 255) / 256, 256>>>(in_w, 512, 2048, winh, winl);               // 2
    wsplit_k<<<(512 * 2048 + 255) / 256, 256>>>(in_w + (size_t)512 * 2048, 512, 2048,
                                                winh + (size_t)2048 * 512,
                                                winl + (size_t)2048 * 512);                 // 3
    wsplit_k<<<(1024 * 512 + 255) / 256, 256>>>(out_w, 1024, 512, wouth, woutl);            // 4
    wsplit_k<<<(1024 * 512 + 255) / 256, 256>>>(out_w + (size_t)1024 * 512, 1024, 512,
                                                wouth + (size_t)512 * 1024,
                                                woutl + (size_t)512 * 1024);                // 5

    // ---- stage 0: h = gelu(x@W_fc1 + b) + posemb  (split-K 2, 128 CTAs) ----
    {
        dim3 g(4, 16, 2);
        hmma_gemm_k<<<g, 256, HSMEM>>>(L, DM, 1024, x, 1024, wfc1h, wfc1l, part, DM,
                                       0, nullptr, nullptr, nullptr, nullptr);              // 6 <- ncu
        reduce_k<<<(L * DM + 255) / 256, 256>>>(part, h, L * DM, DM, 2, 1,
                                                b_fc1, coords, W_pos, b_pos);
    }

    // ---- mamba layers ----
    for (int l = 0; l < 2; l++) {
        const float* cw  = conv_w + (size_t)l * DI * 4;
        const float* cb  = conv_b + (size_t)l * DI;
        const float* xw  = x_w   + (size_t)l * DI * 64;
        const float* dtw = dt_w  + (size_t)l * DTR * DI;
        const float* dtb = dt_b  + (size_t)l * DI;
        const float* al  = A_log + (size_t)l * DI * DS;
        const float* Dl  = Dp    + (size_t)l * DI;
        const float* rw  = rms_w + (size_t)l * DM;

        rms_k<<<L, 128>>>(h, rw, hn);

        { // xz = hn @ in_w : 256 CTAs, no split
            dim3 g(16, 16, 1);
            hmma_gemm_k<<<g, 256, HSMEM>>>(L, 2 * DI, DM, hn, DM,
                                           winh + (size_t)l * 2048 * 512,
                                           winl + (size_t)l * 2048 * 512,
                                           xz, 2 * DI, 0, nullptr, nullptr, nullptr, nullptr);
        }

        conv_silu_k<<<(L * DI) / 256, 256>>>(xz, cw, cb, xi);

        { // dbc = xi @ xw (split-K 8)
            dim3 g(1, L / 128, 8);
            sgemm64_k<<<g, 256>>>(L, 64, DI, xi, DI, xw, 64, part);
            reduce_k<<<(L * 64) / 256, 256>>>(part, dbc, L * 64, 64, 8, 0,
                                              nullptr, nullptr, nullptr, nullptr);
        }

        { // delta = softplus(dbc[:, :32] @ dtw + dtb)
            dim3 g(DI / 128, L / 128);
            delta_k<<<g, 256>>>(dbc, dtw, dtb, delta);
        }

        scan_k<<<DI / 8, 128>>>(delta, xi, dbc, xz, al, Dl, y);

        { // h += y @ out_w (split-K 2, 128 CTAs)
            dim3 g(4, 16, 2);
            hmma_gemm_k<<<g, 256, HSMEM>>>(L, DM, DI, y, DI,
                                           wouth + (size_t)l * 512 * 1024,
                                           woutl + (size_t)l * 512 * 1024,
                                           part, DM, 0, nullptr, nullptr, nullptr, nullptr);
            reduce_k<<<(L * DM + 255) / 256, 256>>>(part, h, L * DM, DM, 2, 2,
                                                    nullptr, nullptr, nullptr, nullptr);
        }
    }

    // ---- LayerNorm ----
    ln_k<<<L, 128>>>(h, ln_w, ln_b, hn);

    // ---- attention: t1 = tanh(hn@Wa1+ba1) (split-K 4, 64 CTAs) ----
    wsplit_k<<<(512 * 128 + 255) / 256, 256>>>(Wa1, 512, 128, wa1h, wa1l);
    {
        dim3 g(1, 16, 4);
        hmma_gemm_k<<<g, 256, HSMEM>>>(L, 128, DM, hn, DM, wa1h, wa1l, part, 128,
                                       0, nullptr, nullptr, nullptr, nullptr);
        reduce_k<<<(L * 128) / 256, 256>>>(part, t1, L * 128, 128, 4, 4,
                                           ba1, nullptr, nullptr, nullptr);
    }
    score_k<<<L / 8, 256>>>(t1, Wa2, ba2, sc);
    softmax_k<<<1, 1024>>>(sc, attw);
    pool_part_k<<<16, 512>>>(attw, hn, part);
    pool_red_k<<<1, 512>>>(part, pooled);

    // ---- ConvTranspose2d stack ----
    convt_k<<<(256 * 16 + 255) / 256, 256>>>(pooled, ct1_w, ct1_b, c1,
                                             512, 256, 1, 4, 1, 0, 1, 256 * 16);
    convt_k<<<(128 * 256 + 255) / 256, 256>>>(c1, ct2_w, ct2_b, c2,
                                              256, 128, 4, 16, 4, 0, 1, 128 * 256);
    convt_k<<<(64 * 1024 + 255) / 256, 256>>>(c2, ct3_w, ct3_b, c3,
                                              128, 64, 16, 32, 2, 1, 1, 64 * 1024);
    convt_k<<<(32 * 4096 + 255) / 256, 256>>>(c3, ct4_w, ct4_b, c4,
                                              64, 32, 32, 64, 2, 1, 1, 32 * 4096);
    convt_k<<<(11 * 16384 + 255) / 256, 256>>>(c4, ct5_w, ct5_b, (float*)d_out,
                                               32, 11, 64, 128, 2, 1, 0, 11 * 16384);
}

// round 7
// speedup vs baseline: 1.4197x; 1.0338x over previous
#include <cuda_runtime.h>
#include <cuda_bf16.h>
#include <math.h>

// ---------------------------------------------------------------------------
// MambaMIL_2D forward. Big GEMMs on HMMA (mma.sync bf16 hi/lo split, fp32 acc),
// 128x64 CTA tiles for 2 CTAs/SM occupancy. Rest SIMT.
// ---------------------------------------------------------------------------

#define L 2048
#define DM 512
#define DI 1024
#define DS 16
#define DTR 32

typedef unsigned long long u64;
typedef unsigned int u32;

// ------------------------------- scratch ----------------------------------
__device__ float g_h   [L * DM];
__device__ float g_hn  [L * DM];
__device__ float g_xz  [L * 2 * DI];
__device__ float g_xi  [L * DI];
__device__ float g_dbc [L * 64];
__device__ float g_delta[L * DI];
__device__ float g_y   [L * DI];
__device__ float g_t1  [L * 128];
__device__ float g_s   [L];
__device__ float g_attw[L];
__device__ float g_pooled[DM];
__device__ float g_part[4 * 1024 * 1024];   // split-K partials
__device__ float g_c1[256 * 16];
__device__ float g_c2[128 * 256];
__device__ float g_c3[64 * 1024];
__device__ float g_c4[32 * 4096];

// split-bf16 transposed weights [N,K]
__device__ __align__(16) __nv_bfloat16 g_wfc1h[512 * 1024], g_wfc1l[512 * 1024];
__device__ __align__(16) __nv_bfloat16 g_winh[2 * 2048 * 512], g_winl[2 * 2048 * 512];
__device__ __align__(16) __nv_bfloat16 g_wouth[2 * 512 * 1024], g_woutl[2 * 512 * 1024];
__device__ __align__(16) __nv_bfloat16 g_wa1h[128 * 512], g_wa1l[128 * 512];

// ------------------------------ math helpers ------------------------------
__device__ __forceinline__ float geluf(float x) {
    return 0.5f * x * (1.f + erff(x * 0.70710678118654752f));
}
__device__ __forceinline__ float softplusf(float x) {
    return (x > 20.f) ? x : log1pf(__expf(x));
}
__device__ __forceinline__ float siluf(float x) {
    return x / (1.f + __expf(-x));
}
__device__ __forceinline__ float ex2f(float x) {
    float r; asm("ex2.approx.ftz.f32 %0, %1;" : "=f"(r) : "f"(x)); return r;
}

// epilogues: 0 none, 1 gelu+bias+posemb, 2 residual-add, 3 bias+softplus, 4 bias+tanh
__device__ __forceinline__ float apply_epi(float v, int row, int col, int ldc,
                                           const float* C, int epi,
                                           const float* bias, const float* aux0,
                                           const float* aux1, const float* aux2) {
    switch (epi) {
        case 1:
            v += bias[col];
            v = geluf(v);
            v += aux0[row * 2 + 0] * aux1[col] + aux0[row * 2 + 1] * aux1[512 + col] + aux2[col];
            return v;
        case 2: return v + C[(size_t)row * ldc + col];
        case 3: return softplusf(v + bias[col]);
        case 4: return tanhf(v + bias[col]);
        default: return v;
    }
}

// --------------------------- HMMA helpers ----------------------------------
__device__ __forceinline__ u32 smem_u32(const void* p) {
    u32 a;
    asm("{ .reg .u64 t; cvta.to.shared.u64 t, %1; cvt.u32.u64 %0, t; }" : "=r"(a) : "l"(p));
    return a;
}
__device__ __forceinline__ void ldsm4(u32* r, u32 addr) {
    asm volatile("ldmatrix.sync.aligned.m8n8.x4.shared.b16 {%0,%1,%2,%3}, [%4];"
                 : "=r"(r[0]), "=r"(r[1]), "=r"(r[2]), "=r"(r[3]) : "r"(addr));
}
__device__ __forceinline__ void mma_bf16(float* c, const u32* a, const u32* b) {
    asm volatile("mma.sync.aligned.m16n8k16.row.col.f32.bf16.bf16.f32 "
                 "{%0,%1,%2,%3}, {%4,%5,%6,%7}, {%8,%9}, {%0,%1,%2,%3};"
                 : "+f"(c[0]), "+f"(c[1]), "+f"(c[2]), "+f"(c[3])
                 : "r"(a[0]), "r"(a[1]), "r"(a[2]), "r"(a[3]), "r"(b[0]), "r"(b[1]));
}
__device__ __forceinline__ void split2(float x, float y, u32& h, u32& l) {
    __nv_bfloat16 hx = __float2bfloat16_rn(x);
    __nv_bfloat16 hy = __float2bfloat16_rn(y);
    __nv_bfloat16 lx = __float2bfloat16_rn(x - __bfloat162float(hx));
    __nv_bfloat16 ly = __float2bfloat16_rn(y - __bfloat162float(hy));
    h = ((u32)__bfloat16_as_ushort(hy) << 16) | (u32)__bfloat16_as_ushort(hx);
    l = ((u32)__bfloat16_as_ushort(ly) << 16) | (u32)__bfloat16_as_ushort(lx);
}

// -------------------- weight transpose + bf16 hi/lo split -------------------
__global__ void wsplit_k(const float* __restrict__ W, int K, int N,
                         __nv_bfloat16* __restrict__ hi, __nv_bfloat16* __restrict__ lo)
{
    int idx = blockIdx.x * 256 + threadIdx.x;
    if (idx >= K * N) return;
    int n = idx / K, k = idx % K;
    float v = W[(size_t)k * N + n];
    __nv_bfloat16 h = __float2bfloat16_rn(v);
    hi[idx] = h;
    lo[idx] = __float2bfloat16_rn(v - __bfloat162float(h));
}

// ------------------------ HMMA split-bf16 GEMM ------------------------------
// C[M,N] = A[M,K](fp32)*B^T, B [N,K] bf16 hi/lo. CTA tile 128x64, BK=32,
// 8 warps (4m x 2n), warp tile 32x32, double-buffered dynamic smem,
// 2 CTAs/SM. Split-K via gridDim.z (raw partials C+z*M*N).
#define SPAD 40
#define A_AB (128 * SPAD * 2)                 // 10240 B
#define B_AB (64 * SPAD * 2)                  // 5120 B
#define BUFB (2 * A_AB + 2 * B_AB)            // 30720 B
#define HSMEM (2 * BUFB)                      // 61440 B

__global__ void __launch_bounds__(256, 2) hmma_gemm_k(
    int M, int N, int K,
    const float* __restrict__ A, int lda,
    const __nv_bfloat16* __restrict__ Bhi, const __nv_bfloat16* __restrict__ Blo,
    float* __restrict__ C, int ldc,
    int epi, const float* __restrict__ bias,
    const float* __restrict__ aux0, const float* __restrict__ aux1,
    const float* __restrict__ aux2)
{
    extern __shared__ char dsm[];
    int tid = threadIdx.x, lane = tid & 31, wid = tid >> 5;
    int bm = blockIdx.y, bn = blockIdx.x, bz = blockIdx.z;
    int slices = gridDim.z;
    int Ks = K / slices;
    int kbase = bz * Ks;
    int wm = wid & 3, wn = wid >> 2;
    int NC = Ks / 32;

    u32 sb = smem_u32(dsm);

    float acc[2][4][4];
#pragma unroll
    for (int mt = 0; mt < 2; mt++)
#pragma unroll
        for (int nt = 0; nt < 4; nt++)
#pragma unroll
            for (int q = 0; q < 4; q++) acc[mt][nt][q] = 0.f;

    float4 pa[4];
    uint4 pbh, pbl;

    auto gload = [&](int kc) {
#pragma unroll
        for (int i = 0; i < 4; i++) {
            int s = tid + i * 256;             // A: 128 rows x 8 float4
            int r = s >> 3, kq = s & 7;
            pa[i] = *(const float4*)(A + (size_t)(bm * 128 + r) * lda + kbase + kc * 32 + kq * 4);
        }
        {
            int r = tid >> 2, kq = tid & 3;    // B: 64 rows x 4 uint4
            size_t off = (size_t)(bn * 64 + r) * K + kbase + kc * 32 + kq * 8;
            pbh = *(const uint4*)(Bhi + off);
            pbl = *(const uint4*)(Blo + off);
        }
    };
    auto sstore = [&](int buf) {
        char* bufp = dsm + buf * BUFB;
#pragma unroll
        for (int i = 0; i < 4; i++) {
            int s = tid + i * 256;
            int r = s >> 3, kq = s & 7;
            u32 h0, l0, h1, l1;
            split2(pa[i].x, pa[i].y, h0, l0);
            split2(pa[i].z, pa[i].w, h1, l1);
            *(uint2*)(bufp + (r * SPAD + kq * 4) * 2)         = make_uint2(h0, h1);
            *(uint2*)(bufp + A_AB + (r * SPAD + kq * 4) * 2)  = make_uint2(l0, l1);
        }
        {
            int r = tid >> 2, kq = tid & 3;
            *(uint4*)(bufp + 2 * A_AB + (r * SPAD + kq * 8) * 2)        = pbh;
            *(uint4*)(bufp + 2 * A_AB + B_AB + (r * SPAD + kq * 8) * 2) = pbl;
        }
    };

    gload(0);
    sstore(0);
    __syncthreads();

    for (int kc = 0; kc < NC; kc++) {
        int buf = kc & 1;
        if (kc + 1 < NC) gload(kc + 1);
        u32 bAh = sb + buf * BUFB;
        u32 bAl = bAh + A_AB;
        u32 bBh = bAh + 2 * A_AB;
        u32 bBl = bBh + B_AB;
#pragma unroll
        for (int ks = 0; ks < 2; ks++) {
            u32 ah[2][4], al[2][4];
#pragma unroll
            for (int mt = 0; mt < 2; mt++) {
                int row = wm * 32 + mt * 16 + ((lane >> 3) & 1) * 8 + (lane & 7);
                int kcol = ks * 16 + (lane >> 4) * 8;
                u32 off = (u32)(row * SPAD + kcol) * 2;
                ldsm4(ah[mt], bAh + off);
                ldsm4(al[mt], bAl + off);
            }
            u32 bh[4][2], bl[4][2];
#pragma unroll
            for (int p = 0; p < 2; p++) {
                int n = wn * 32 + p * 16 + (lane >> 4) * 8 + (lane & 7);
                int kcol = ks * 16 + ((lane >> 3) & 1) * 8;
                u32 off = (u32)(n * SPAD + kcol) * 2;
                u32 r4[4];
                ldsm4(r4, bBh + off);
                bh[p * 2][0] = r4[0]; bh[p * 2][1] = r4[1];
                bh[p * 2 + 1][0] = r4[2]; bh[p * 2 + 1][1] = r4[3];
                ldsm4(r4, bBl + off);
                bl[p * 2][0] = r4[0]; bl[p * 2][1] = r4[1];
                bl[p * 2 + 1][0] = r4[2]; bl[p * 2 + 1][1] = r4[3];
            }
#pragma unroll
            for (int mt = 0; mt < 2; mt++)
#pragma unroll
                for (int nt = 0; nt < 4; nt++) {
                    mma_bf16(acc[mt][nt], ah[mt], bh[nt]);
                    mma_bf16(acc[mt][nt], ah[mt], bl[nt]);
                    mma_bf16(acc[mt][nt], al[mt], bh[nt]);
                }
        }
        if (kc + 1 < NC) sstore(1 - buf);
        __syncthreads();
    }

    if (slices == 1) {
#pragma unroll
        for (int mt = 0; mt < 2; mt++) {
            int row0 = bm * 128 + wm * 32 + mt * 16 + (lane >> 2);
#pragma unroll
            for (int nt = 0; nt < 4; nt++) {
                int col = bn * 64 + wn * 32 + nt * 8 + (lane & 3) * 2;
                C[(size_t)row0 * ldc + col] =
                    apply_epi(acc[mt][nt][0], row0, col, ldc, C, epi, bias, aux0, aux1, aux2);
                C[(size_t)row0 * ldc + col + 1] =
                    apply_epi(acc[mt][nt][1], row0, col + 1, ldc, C, epi, bias, aux0, aux1, aux2);
                int row1 = row0 + 8;
                C[(size_t)row1 * ldc + col] =
                    apply_epi(acc[mt][nt][2], row1, col, ldc, C, epi, bias, aux0, aux1, aux2);
                C[(size_t)row1 * ldc + col + 1] =
                    apply_epi(acc[mt][nt][3], row1, col + 1, ldc, C, epi, bias, aux0, aux1, aux2);
            }
        }
    } else {
        float* Cp = C + (size_t)bz * M * N;
#pragma unroll
        for (int mt = 0; mt < 2; mt++) {
            int row0 = bm * 128 + wm * 32 + mt * 16 + (lane >> 2);
#pragma unroll
            for (int nt = 0; nt < 4; nt++) {
                int col = bn * 64 + wn * 32 + nt * 8 + (lane & 3) * 2;
                Cp[(size_t)row0 * N + col]           = acc[mt][nt][0];
                Cp[(size_t)row0 * N + col + 1]       = acc[mt][nt][1];
                Cp[(size_t)(row0 + 8) * N + col]     = acc[mt][nt][2];
                Cp[(size_t)(row0 + 8) * N + col + 1] = acc[mt][nt][3];
            }
        }
    }
}

// reduce split-K partials + full epilogue support
__global__ void reduce_k(const float* __restrict__ part, float* __restrict__ out,
                         int MN, int N, int slices, int epi,
                         const float* __restrict__ bias, const float* __restrict__ aux0,
                         const float* __restrict__ aux1, const float* __restrict__ aux2)
{
    int idx = blockIdx.x * blockDim.x + threadIdx.x;
    if (idx >= MN) return;
    float v = 0.f;
    for (int s = 0; s < slices; s++) v += part[(size_t)s * MN + idx];
    int row = idx / N, col = idx % N;
    switch (epi) {
        case 1:
            v += bias[col];
            v = geluf(v);
            v += aux0[row * 2 + 0] * aux1[col] + aux0[row * 2 + 1] * aux1[512 + col] + aux2[col];
            break;
        case 2: v += out[idx]; break;
        case 4: v = tanhf(v + bias[col]); break;
        default: break;
    }
    out[idx] = v;
}

// ------------------------ SIMT SGEMM 128x64 (dbc GEMM) ---------------------
__global__ __launch_bounds__(256, 2) void sgemm64_k(
    int M, int N, int K,
    const float* __restrict__ A, int lda,
    const float* __restrict__ B, int ldb,
    float* __restrict__ C)
{
    __shared__ float As[16][132];
    __shared__ float Bs[16][64];
    int tid = threadIdx.x;
    int bm = blockIdx.y, bn = blockIdx.x, bz = blockIdx.z;
    int slices = gridDim.z;
    int Ks = K / slices;
    int kbase = bz * Ks;

    int aRow = tid >> 1;
    int aCol = (tid & 1) * 8;
    int bRow = tid >> 4;
    int bCol = (tid & 15) * 4;
    int tr = tid >> 4;
    int tc = tid & 15;

    const float* Ap = A + (size_t)(bm * 128 + aRow) * lda + kbase + aCol;
    const float* Bp = B + (size_t)(kbase + bRow) * ldb + bn * 64 + bCol;

    float acc[8][4];
#pragma unroll
    for (int i = 0; i < 8; i++)
#pragma unroll
        for (int j = 0; j < 4; j++) acc[i][j] = 0.f;

    for (int k0 = 0; k0 < Ks; k0 += 16) {
        float4 a0 = *(const float4*)(Ap + k0);
        float4 a1 = *(const float4*)(Ap + k0 + 4);
        float4 b0 = *(const float4*)(Bp + (size_t)k0 * ldb);
        As[aCol + 0][aRow] = a0.x; As[aCol + 1][aRow] = a0.y;
        As[aCol + 2][aRow] = a0.z; As[aCol + 3][aRow] = a0.w;
        As[aCol + 4][aRow] = a1.x; As[aCol + 5][aRow] = a1.y;
        As[aCol + 6][aRow] = a1.z; As[aCol + 7][aRow] = a1.w;
        *(float4*)&Bs[bRow][bCol] = b0;
        __syncthreads();
#pragma unroll
        for (int kk = 0; kk < 16; kk++) {
            float4 ra0 = *(const float4*)&As[kk][tr * 4];
            float4 ra1 = *(const float4*)&As[kk][tr * 4 + 64];
            float4 rb0 = *(const float4*)&Bs[kk][tc * 4];
            float ra[8] = {ra0.x, ra0.y, ra0.z, ra0.w, ra1.x, ra1.y, ra1.z, ra1.w};
            float rb[4] = {rb0.x, rb0.y, rb0.z, rb0.w};
#pragma unroll
            for (int i = 0; i < 8; i++)
#pragma unroll
                for (int j = 0; j < 4; j++)
                    acc[i][j] = fmaf(ra[i], rb[j], acc[i][j]);
        }
        __syncthreads();
    }

    float* Cp = C + (size_t)bz * M * N;
#pragma unroll
    for (int i = 0; i < 8; i++) {
        int row = bm * 128 + ((i < 4) ? (tr * 4 + i) : (64 + tr * 4 + i - 4));
#pragma unroll
        for (int j = 0; j < 4; j++) {
            int col = bn * 64 + tc * 4 + j;
            Cp[(size_t)row * N + col] = acc[i][j];
        }
    }
}

// --------------------------- delta GEMM (K=32) ------------------------------
__global__ __launch_bounds__(256) void delta_k(
    const float* __restrict__ dbc, const float* __restrict__ dtw,
    const float* __restrict__ dtb, float* __restrict__ delta)
{
    __shared__ float As[128][33];
    __shared__ float Bs[32][128];
    int tid = threadIdx.x;
    int bm = blockIdx.y, bn = blockIdx.x;
#pragma unroll
    for (int i = 0; i < 16; i++) {
        int e = tid + i * 256;
        int r = e >> 5, c = e & 31;
        As[r][c] = dbc[(size_t)(bm * 128 + r) * 64 + c];
    }
#pragma unroll
    for (int i = 0; i < 16; i++) {
        int e = tid + i * 256;
        int r = e >> 7, c = e & 127;
        Bs[r][c] = dtw[(size_t)r * DI + bn * 128 + c];
    }
    __syncthreads();
    int tr = tid >> 4, tc = tid & 15;
    float acc[8][8];
#pragma unroll
    for (int i = 0; i < 8; i++)
#pragma unroll
        for (int j = 0; j < 8; j++) acc[i][j] = 0.f;
#pragma unroll
    for (int k = 0; k < 32; k++) {
        float ra[8], rb[8];
#pragma unroll
        for (int i = 0; i < 8; i++) ra[i] = As[tr * 8 + i][k];
#pragma unroll
        for (int j = 0; j < 8; j++) rb[j] = Bs[k][tc * 8 + j];
#pragma unroll
        for (int i = 0; i < 8; i++)
#pragma unroll
            for (int j = 0; j < 8; j++) acc[i][j] = fmaf(ra[i], rb[j], acc[i][j]);
    }
#pragma unroll
    for (int i = 0; i < 8; i++) {
        int row = bm * 128 + tr * 8 + i;
#pragma unroll
        for (int j = 0; j < 8; j++) {
            int col = bn * 128 + tc * 8 + j;
            delta[(size_t)row * DI + col] = softplusf(acc[i][j] + dtb[col]);
        }
    }
}

// ------------------------------- RMSNorm -----------------------------------
__global__ __launch_bounds__(128) void rms_k(const float* __restrict__ h,
                                             const float* __restrict__ w,
                                             float* __restrict__ out)
{
    int t = blockIdx.x, tid = threadIdx.x;
    float v[4]; float ss = 0.f;
#pragma unroll
    for (int i = 0; i < 4; i++) {
        v[i] = h[(size_t)t * DM + tid + i * 128];
        ss += v[i] * v[i];
    }
#pragma unroll
    for (int off = 16; off > 0; off >>= 1) ss += __shfl_xor_sync(0xffffffffu, ss, off);
    __shared__ float sm[4];
    if ((tid & 31) == 0) sm[tid >> 5] = ss;
    __syncthreads();
    float tot = sm[0] + sm[1] + sm[2] + sm[3];
    float r = rsqrtf(tot / (float)DM + 1e-5f);
#pragma unroll
    for (int i = 0; i < 4; i++) {
        int c = tid + i * 128;
        out[(size_t)t * DM + c] = v[i] * r * w[c];
    }
}

// ------------------------------- LayerNorm ---------------------------------
__global__ __launch_bounds__(128) void ln_k(const float* __restrict__ h,
                                            const float* __restrict__ w,
                                            const float* __restrict__ b,
                                            float* __restrict__ out)
{
    int t = blockIdx.x, tid = threadIdx.x;
    float v[4]; float s1 = 0.f, s2 = 0.f;
#pragma unroll
    for (int i = 0; i < 4; i++) {
        v[i] = h[(size_t)t * DM + tid + i * 128];
        s1 += v[i]; s2 += v[i] * v[i];
    }
#pragma unroll
    for (int off = 16; off > 0; off >>= 1) {
        s1 += __shfl_xor_sync(0xffffffffu, s1, off);
        s2 += __shfl_xor_sync(0xffffffffu, s2, off);
    }
    __shared__ float a1[4], a2[4];
    if ((tid & 31) == 0) { a1[tid >> 5] = s1; a2[tid >> 5] = s2; }
    __syncthreads();
    s1 = a1[0] + a1[1] + a1[2] + a1[3];
    s2 = a2[0] + a2[1] + a2[2] + a2[3];
    float mean = s1 / (float)DM;
    float var = s2 / (float)DM - mean * mean;
    float r = rsqrtf(var + 1e-5f);
#pragma unroll
    for (int i = 0; i < 4; i++) {
        int c = tid + i * 128;
        out[(size_t)t * DM + c] = (v[i] - mean) * r * w[c] + b[c];
    }
}

// --------------------------- depthwise conv + silu -------------------------
__global__ __launch_bounds__(256) void conv_silu_k(const float* __restrict__ xz,
                                                   const float* __restrict__ cw,
                                                   const float* __restrict__ cb,
                                                   float* __restrict__ xi)
{
    int idx = blockIdx.x * 256 + threadIdx.x;
    int t = idx >> 10, d = idx & 1023;
    float w0 = cw[d * 4 + 0], w1 = cw[d * 4 + 1], w2 = cw[d * 4 + 2], w3 = cw[d * 4 + 3];
    float acc = cb[d];
    if (t >= 3) acc = fmaf(xz[(size_t)(t - 3) * 2048 + d], w0, acc);
    if (t >= 2) acc = fmaf(xz[(size_t)(t - 2) * 2048 + d], w1, acc);
    if (t >= 1) acc = fmaf(xz[(size_t)(t - 1) * 2048 + d], w2, acc);
    acc = fmaf(xz[(size_t)t * 2048 + d], w3, acc);
    xi[idx] = siluf(acc);
}

// ------------------------------ selective scan ------------------------------
__global__ __launch_bounds__(128) void scan_k(
    const float* __restrict__ delta, const float* __restrict__ xi,
    const float* __restrict__ dbc, const float* __restrict__ xz,
    const float* __restrict__ alog, const float* __restrict__ Dp,
    float* __restrict__ y)
{
    __shared__ float sd[64][8], sx[64][8], sz[64][8];
    __shared__ float sBC[64][32];
    __shared__ float sp[64][8][16];
    __shared__ float sDv[8];
    int tid = threadIdx.x;
    int d0 = blockIdx.x * 8;
    int dloc = tid >> 4;
    int n = tid & 15;
    int d = d0 + dloc;
    float AdnL2 = -__expf(alog[d * DS + n]) * 1.4426950408889634f;
    if (tid < 8) sDv[tid] = Dp[d0 + tid];
    float h = 0.f;

    for (int t0 = 0; t0 < L; t0 += 64) {
#pragma unroll
        for (int i = 0; i < 4; i++) {
            int e = tid + i * 128; int r = e >> 3, c = e & 7;
            sd[r][c] = delta[(size_t)(t0 + r) * DI + d0 + c];
            sx[r][c] = xi[(size_t)(t0 + r) * DI + d0 + c];
            sz[r][c] = xz[(size_t)(t0 + r) * 2048 + DI + d0 + c];
        }
#pragma unroll
        for (int i = 0; i < 16; i++) {
            int e = tid + i * 128; int r = e >> 5, c = e & 31;
            sBC[r][c] = dbc[(size_t)(t0 + r) * 64 + 32 + c];
        }
        __syncthreads();
#pragma unroll 4
        for (int tt = 0; tt < 64; tt++) {
            float dl = sd[tt][dloc];
            float xv = sx[tt][dloc];
            float a = ex2f(dl * AdnL2);
            float bx = dl * xv * sBC[tt][n];
            h = fmaf(a, h, bx);
            sp[tt][dloc][n] = h * sBC[tt][16 + n];
        }
        __syncthreads();
#pragma unroll
        for (int i = 0; i < 4; i++) {
            int e = tid + i * 128; int r = e >> 3, c = e & 7;
            float s = 0.f;
#pragma unroll
            for (int nn = 0; nn < 16; nn++) s += sp[r][c][nn];
            float zz = sz[r][c];
            y[(size_t)(t0 + r) * DI + d0 + c] = (s + sx[r][c] * sDv[c]) * siluf(zz);
        }
        __syncthreads();
    }
}

// -------------------------- attention score / softmax / pool ---------------
__global__ __launch_bounds__(256) void score_k(const float* __restrict__ t1,
                                               const float* __restrict__ Wa2,
                                               const float* __restrict__ ba2,
                                               float* __restrict__ s)
{
    int gw = (blockIdx.x * 256 + threadIdx.x) >> 5;
    int lane = threadIdx.x & 31;
    const float* row = t1 + (size_t)gw * 128;
    float acc = 0.f;
#pragma unroll
    for (int i = 0; i < 4; i++) acc = fmaf(row[lane + i * 32], Wa2[lane + i * 32], acc);
#pragma unroll
    for (int off = 16; off > 0; off >>= 1) acc += __shfl_xor_sync(0xffffffffu, acc, off);
    if (lane == 0) s[gw] = acc + ba2[0];
}

__global__ __launch_bounds__(1024) void softmax_k(const float* __restrict__ s,
                                                  float* __restrict__ w)
{
    int tid = threadIdx.x;
    __shared__ float red[32];
    __shared__ float bres;
    float a = s[tid], b = s[tid + 1024];
    float m = fmaxf(a, b);
#pragma unroll
    for (int off = 16; off > 0; off >>= 1) m = fmaxf(m, __shfl_xor_sync(0xffffffffu, m, off));
    if ((tid & 31) == 0) red[tid >> 5] = m;
    __syncthreads();
    if (tid < 32) {
        float x = red[tid];
#pragma unroll
        for (int off = 16; off > 0; off >>= 1) x = fmaxf(x, __shfl_xor_sync(0xffffffffu, x, off));
        if (tid == 0) bres = x;
    }
    __syncthreads();
    float M = bres;
    float ea = __expf(a - M), eb = __expf(b - M);
    float ss = ea + eb;
#pragma unroll
    for (int off = 16; off > 0; off >>= 1) ss += __shfl_xor_sync(0xffffffffu, ss, off);
    __syncthreads();
    if ((tid & 31) == 0) red[tid >> 5] = ss;
    __syncthreads();
    if (tid < 32) {
        float x = red[tid];
#pragma unroll
        for (int off = 16; off > 0; off >>= 1) x += __shfl_xor_sync(0xffffffffu, x, off);
        if (tid == 0) bres = x;
    }
    __syncthreads();
    float inv = 1.f / bres;
    w[tid] = ea * inv;
    w[tid + 1024] = eb * inv;
}

__global__ __launch_bounds__(512) void pool_part_k(const float* __restrict__ attw,
                                                   const float* __restrict__ hn,
                                                   float* __restrict__ part)
{
    int b = blockIdx.x;
    int c = threadIdx.x;
    float acc = 0.f;
    int t0 = b * 128;
#pragma unroll 8
    for (int t = t0; t < t0 + 128; t++) acc = fmaf(attw[t], hn[(size_t)t * DM + c], acc);
    part[b * DM + c] = acc;
}

__global__ __launch_bounds__(512) void pool_red_k(const float* __restrict__ part,
                                                  float* __restrict__ pooled)
{
    int c = threadIdx.x;
    float acc = 0.f;
#pragma unroll
    for (int s = 0; s < 16; s++) acc += part[s * DM + c];
    pooled[c] = acc;
}

// ---------------------------- ConvTranspose2d ------------------------------
__global__ void convt_k(const float* __restrict__ in, const float* __restrict__ w,
                        const float* __restrict__ b, float* __restrict__ out,
                        int Cin, int Cout, int Hin, int Hout, int S, int P,
                        int do_relu, int total)
{
    int idx = blockIdx.x * blockDim.x + threadIdx.x;
    if (idx >= total) return;
    int hw = Hout * Hout;
    int co = idx / hw;
    int r = idx % hw;
    int oy = r / Hout, ox = r % Hout;
    float acc = b[co];
    for (int ky = 0; ky < 4; ky++) {
        int ry = oy + P - ky;
        if (ry < 0 || (ry % S)) continue;
        int iy = ry / S;
        if (iy >= Hin) continue;
        for (int kx = 0; kx < 4; kx++) {
            int rx = ox + P - kx;
            if (rx < 0 || (rx % S)) continue;
            int ix = rx / S;
            if (ix >= Hin) continue;
            const float* wp = w + co * 16 + ky * 4 + kx;
            const float* ip = in + iy * Hin + ix;
            float ps = 0.f;
            for (int ci = 0; ci < Cin; ci++)
                ps = fmaf(ip[ci * Hin * Hin], wp[(size_t)ci * Cout * 16], ps);
            acc += ps;
        }
    }
    out[idx] = do_relu ? fmaxf(acc, 0.f) : acc;
}

// ------------------------------- launcher ----------------------------------
extern "C" void kernel_launch(void* const* d_in, const int* in_sizes, int n_in,
                              void* d_out, int out_size)
{
    const float* x       = (const float*)d_in[0];
    const float* coords  = (const float*)d_in[1];
    const float* W_fc1   = (const float*)d_in[2];
    const float* b_fc1   = (const float*)d_in[3];
    const float* W_pos   = (const float*)d_in[4];
    const float* b_pos   = (const float*)d_in[5];
    const float* in_w    = (const float*)d_in[6];
    const float* conv_w  = (const float*)d_in[7];
    const float* conv_b  = (const float*)d_in[8];
    const float* x_w     = (const float*)d_in[9];
    const float* dt_w    = (const float*)d_in[10];
    const float* dt_b    = (const float*)d_in[11];
    const float* A_log   = (const float*)d_in[12];
    const float* Dp      = (const float*)d_in[13];
    const float* out_w   = (const float*)d_in[14];
    const float* rms_w   = (const float*)d_in[15];
    const float* ln_w    = (const float*)d_in[16];
    const float* ln_b    = (const float*)d_in[17];
    const float* Wa1     = (const float*)d_in[18];
    const float* ba1     = (const float*)d_in[19];
    const float* Wa2     = (const float*)d_in[20];
    const float* ba2     = (const float*)d_in[21];
    const float* ct1_w   = (const float*)d_in[22];
    const float* ct1_b   = (const float*)d_in[23];
    const float* ct2_w   = (const float*)d_in[24];
    const float* ct2_b   = (const float*)d_in[25];
    const float* ct3_w   = (const float*)d_in[26];
    const float* ct3_b   = (const float*)d_in[27];
    const float* ct4_w   = (const float*)d_in[28];
    const float* ct4_b   = (const float*)d_in[29];
    const float* ct5_w   = (const float*)d_in[30];
    const float* ct5_b   = (const float*)d_in[31];

    float *h, *hn, *xz, *xi, *dbc, *delta, *y, *t1, *sc, *attw, *pooled, *part;
    float *c1, *c2, *c3, *c4;
    __nv_bfloat16 *wfc1h, *wfc1l, *winh, *winl, *wouth, *woutl, *wa1h, *wa1l;
    cudaGetSymbolAddress((void**)&h, g_h);
    cudaGetSymbolAddress((void**)&hn, g_hn);
    cudaGetSymbolAddress((void**)&xz, g_xz);
    cudaGetSymbolAddress((void**)&xi, g_xi);
    cudaGetSymbolAddress((void**)&dbc, g_dbc);
    cudaGetSymbolAddress((void**)&delta, g_delta);
    cudaGetSymbolAddress((void**)&y, g_y);
    cudaGetSymbolAddress((void**)&t1, g_t1);
    cudaGetSymbolAddress((void**)&sc, g_s);
    cudaGetSymbolAddress((void**)&attw, g_attw);
    cudaGetSymbolAddress((void**)&pooled, g_pooled);
    cudaGetSymbolAddress((void**)&part, g_part);
    cudaGetSymbolAddress((void**)&c1, g_c1);
    cudaGetSymbolAddress((void**)&c2, g_c2);
    cudaGetSymbolAddress((void**)&c3, g_c3);
    cudaGetSymbolAddress((void**)&c4, g_c4);
    cudaGetSymbolAddress((void**)&wfc1h, g_wfc1h);
    cudaGetSymbolAddress((void**)&wfc1l, g_wfc1l);
    cudaGetSymbolAddress((void**)&winh, g_winh);
    cudaGetSymbolAddress((void**)&winl, g_winl);
    cudaGetSymbolAddress((void**)&wouth, g_wouth);
    cudaGetSymbolAddress((void**)&woutl, g_woutl);
    cudaGetSymbolAddress((void**)&wa1h, g_wa1h);
    cudaGetSymbolAddress((void**)&wa1l, g_wa1l);

    cudaFuncSetAttribute(hmma_gemm_k, cudaFuncAttributeMaxDynamicSharedMemorySize, HSMEM);

    // ---- 4 wsplits, then my launch #5 = fc1 HMMA (process #6 -> ncu) ----
    wsplit_k<<<(1024 * 512 + 255) / 256, 256>>>(W_fc1, 1024, 512, wfc1h, wfc1l);            // 1
    wsplit_k<<<(512 * 2048 + 255) / 256, 256>>>(in_w, 512, 2048, winh, winl);               // 2
    wsplit_k<<<(512 * 2048 + 255) / 256, 256>>>(in_w + (size_t)512 * 2048, 512, 2048,
                                                winh + (size_t)2048 * 512,
                                                winl + (size_t)2048 * 512);                 // 3
    wsplit_k<<<(1024 * 512 + 255) / 256, 256>>>(out_w, 1024, 512, wouth, woutl);            // 4

    // ---- stage 0: h = gelu(x@W_fc1 + b) + posemb  (split-K 2, 256 CTAs) ----
    {
        dim3 g(8, 16, 2);
        hmma_gemm_k<<<g, 256, HSMEM>>>(L, DM, 1024, x, 1024, wfc1h, wfc1l, part, DM,
                                       0, nullptr, nullptr, nullptr, nullptr);              // 5 <- ncu target
        reduce_k<<<(L * DM + 255) / 256, 256>>>(part, h, L * DM, DM, 2, 1,
                                                b_fc1, coords, W_pos, b_pos);
    }

    // deferred weight splits
    wsplit_k<<<(1024 * 512 + 255) / 256, 256>>>(out_w + (size_t)1024 * 512, 1024, 512,
                                                wouth + (size_t)512 * 1024,
                                                woutl + (size_t)512 * 1024);
    wsplit_k<<<(512 * 128 + 255) / 256, 256>>>(Wa1, 512, 128, wa1h, wa1l);

    // ---- mamba layers ----
    for (int l = 0; l < 2; l++) {
        const float* cw  = conv_w + (size_t)l * DI * 4;
        const float* cb  = conv_b + (size_t)l * DI;
        const float* xw  = x_w   + (size_t)l * DI * 64;
        const float* dtw = dt_w  + (size_t)l * DTR * DI;
        const float* dtb = dt_b  + (size_t)l * DI;
        const float* al  = A_log + (size_t)l * DI * DS;
        const float* Dl  = Dp    + (size_t)l * DI;
        const float* rw  = rms_w + (size_t)l * DM;

        rms_k<<<L, 128>>>(h, rw, hn);

        { // xz = hn @ in_w : 512 CTAs
            dim3 g(32, 16, 1);
            hmma_gemm_k<<<g, 256, HSMEM>>>(L, 2 * DI, DM, hn, DM,
                                           winh + (size_t)l * 2048 * 512,
                                           winl + (size_t)l * 2048 * 512,
                                           xz, 2 * DI, 0, nullptr, nullptr, nullptr, nullptr);
        }

        conv_silu_k<<<(L * DI) / 256, 256>>>(xz, cw, cb, xi);

        { // dbc = xi @ xw (split-K 8)
            dim3 g(1, L / 128, 8);
            sgemm64_k<<<g, 256>>>(L, 64, DI, xi, DI, xw, 64, part);
            reduce_k<<<(L * 64) / 256, 256>>>(part, dbc, L * 64, 64, 8, 0,
                                              nullptr, nullptr, nullptr, nullptr);
        }

        { // delta = softplus(dbc[:, :32] @ dtw + dtb)
            dim3 g(DI / 128, L / 128);
            delta_k<<<g, 256>>>(dbc, dtw, dtb, delta);
        }

        scan_k<<<DI / 8, 128>>>(delta, xi, dbc, xz, al, Dl, y);

        { // h += y @ out_w (split-K 2, 256 CTAs)
            dim3 g(8, 16, 2);
            hmma_gemm_k<<<g, 256, HSMEM>>>(L, DM, DI, y, DI,
                                           wouth + (size_t)l * 512 * 1024,
                                           woutl + (size_t)l * 512 * 1024,
                                           part, DM, 0, nullptr, nullptr, nullptr, nullptr);
            reduce_k<<<(L * DM + 255) / 256, 256>>>(part, h, L * DM, DM, 2, 2,
                                                    nullptr, nullptr, nullptr, nullptr);
        }
    }

    // ---- LayerNorm ----
    ln_k<<<L, 128>>>(h, ln_w, ln_b, hn);

    // ---- attention: t1 = tanh(hn@Wa1+ba1) (split-K 4, 128 CTAs) ----
    {
        dim3 g(2, 16, 4);
        hmma_gemm_k<<<g, 256, HSMEM>>>(L, 128, DM, hn, DM, wa1h, wa1l, part, 128,
                                       0, nullptr, nullptr, nullptr, nullptr);
        reduce_k<<<(L * 128) / 256, 256>>>(part, t1, L * 128, 128, 4, 4,
                                           ba1, nullptr, nullptr, nullptr);
    }
    score_k<<<L / 8, 256>>>(t1, Wa2, ba2, sc);
    softmax_k<<<1, 1024>>>(sc, attw);
    pool_part_k<<<16, 512>>>(attw, hn, part);
    pool_red_k<<<1, 512>>>(part, pooled);

    // ---- ConvTranspose2d stack ----
    convt_k<<<(256 * 16 + 255) / 256, 256>>>(pooled, ct1_w, ct1_b, c1,
                                             512, 256, 1, 4, 1, 0, 1, 256 * 16);
    convt_k<<<(128 * 256 + 255) / 256, 256>>>(c1, ct2_w, ct2_b, c2,
                                              256, 128, 4, 16, 4, 0, 1, 128 * 256);
    convt_k<<<(64 * 1024 + 255) / 256, 256>>>(c2, ct3_w, ct3_b, c3,
                                              128, 64, 16, 32, 2, 1, 1, 64 * 1024);
    convt_k<<<(32 * 4096 + 255) / 256, 256>>>(c3, ct4_w, ct4_b, c4,
                                              64, 32, 32, 64, 2, 1, 1, 32 * 4096);
    convt_k<<<(11 * 16384 + 255) / 256, 256>>>(c4, ct5_w, ct5_b, (float*)d_out,
                                               32, 11, 64, 128, 2, 1, 0, 11 * 16384);
}